// round 4
// baseline (speedup 1.0000x reference)
#include <cuda_runtime.h>
#include <cstddef>

#define BATCH   64
#define SRC_T   128
#define DEC_T   127
#define EMB     512
#define HID     512
#define G3      1536
#define VOCAB   10000
#define NLAYERS 2
#define RBLK    128   // persistent recurrence blocks (<= 148 SMs, guaranteed co-resident)

// ---------------- scratch (device globals; no runtime allocation) ----------------
__device__ float g_X   [BATCH*SRC_T*EMB];     // ping
__device__ float g_Ybuf[BATCH*SRC_T*EMB];     // pong
__device__ float g_gi  [BATCH*SRC_T*G3];      // precomputed input gates
__device__ float g_WTih[EMB*G3];              // transposed Wih of current layer
__device__ float g_WThh[HID*G3];              // transposed Whh of current layer
__device__ float g_fcT [HID*VOCAB];           // transposed fc_W
__device__ float g_h   [BATCH*HID];           // recurrent state
__device__ float g_hid_enc[NLAYERS*BATCH*HID];
__device__ float g_hid_dec[NLAYERS*BATCH*HID];
__device__ float g_ghp [8][BATCH*G3];         // K-split partial sums of h@WhhT
__device__ unsigned g_bar_count;
__device__ unsigned g_bar_gen;

// ---------------- grid barrier (all RBLK blocks resident) ----------------
__device__ __forceinline__ void gbar() {
    __syncthreads();
    if (threadIdx.x == 0) {
        __threadfence();
        unsigned gen = atomicAdd(&g_bar_gen, 0u);
        if (atomicAdd(&g_bar_count, 1u) == RBLK - 1u) {
            atomicExch(&g_bar_count, 0u);
            __threadfence();
            atomicExch(&g_bar_gen, gen + 1u);
        } else {
            while (atomicAdd(&g_bar_gen, 0u) == gen) __nanosleep(64);
        }
        __threadfence();
    }
    __syncthreads();
}

// ---------------- embedding gather ----------------
// rows m = b*T + t ; token = tok[b*tokStride + t] ; X[m][:] = emb[token][:]
__global__ void embed_kernel(const int* __restrict__ tok, int tokStride,
                             const float* __restrict__ emb,
                             float* __restrict__ X, int T) {
    int m = blockIdx.x;
    int b = m / T, t = m - b * T;
    int v = tok[b * tokStride + t];
    const float4* s = (const float4*)(emb + (size_t)v * EMB);
    float4* d = (float4*)(X + (size_t)m * EMB);
    d[threadIdx.x] = s[threadIdx.x];
}

// ---------------- transpose: D[C][R] = S[R][C] ----------------
__global__ void transpose_kernel(const float* __restrict__ S, float* __restrict__ D,
                                 int R, int C) {
    __shared__ float tile[32][33];
    int c0 = blockIdx.x * 32, r0 = blockIdx.y * 32;
    int x = threadIdx.x, y = threadIdx.y;
    #pragma unroll
    for (int i = 0; i < 32; i += 8) {
        int r = r0 + y + i, c = c0 + x;
        if (r < R && c < C) tile[y + i][x] = S[(size_t)r * C + c];
    }
    __syncthreads();
    #pragma unroll
    for (int i = 0; i < 32; i += 8) {
        int c = c0 + y + i, r = r0 + x;
        if (r < R && c < C) D[(size_t)c * R + r] = tile[x][y + i];
    }
}

// ---------------- fp32 SGEMM: C[M,N] = A[M,K] @ Bm[K,N] + bias[N] ----------------
// cmode 0: C row = m.  cmode 1 (FC head): m = b*127+t -> C row = b*128 + t + 1.
__global__ void __launch_bounds__(256) sgemm_bias(
    const float* __restrict__ A, const float* __restrict__ Bm,
    float* __restrict__ C, const float* __restrict__ bias,
    int M, int N, int K, int cmode) {
    const int BM = 128, BN = 128, BK = 8;
    __shared__ float As[BK][BM];
    __shared__ float Bs[BK][BN];
    int tid = threadIdx.x;
    int tx = tid & 15, ty = tid >> 4;
    int m_base = blockIdx.y * BM, n_base = blockIdx.x * BN;
    int arow = tid >> 1, acol = (tid & 1) * 4;
    int brow = tid >> 5, bcol = (tid & 31) * 4;
    float acc[8][8] = {};
    for (int k0 = 0; k0 < K; k0 += BK) {
        float4 av = make_float4(0.f, 0.f, 0.f, 0.f);
        int am = m_base + arow;
        if (am < M) av = *(const float4*)(A + (size_t)am * K + k0 + acol);
        As[acol + 0][arow] = av.x; As[acol + 1][arow] = av.y;
        As[acol + 2][arow] = av.z; As[acol + 3][arow] = av.w;
        float4 bv = make_float4(0.f, 0.f, 0.f, 0.f);
        int bn = n_base + bcol;
        if (bn < N) bv = *(const float4*)(Bm + (size_t)(k0 + brow) * N + bn);
        *(float4*)&Bs[brow][bcol] = bv;
        __syncthreads();
        #pragma unroll
        for (int k = 0; k < BK; k++) {
            float a[8], b[8];
            #pragma unroll
            for (int i = 0; i < 4; i++) {
                a[i]     = As[k][ty * 4 + i];
                a[4 + i] = As[k][64 + ty * 4 + i];
                b[i]     = Bs[k][tx * 4 + i];
                b[4 + i] = Bs[k][64 + tx * 4 + i];
            }
            #pragma unroll
            for (int i = 0; i < 8; i++)
                #pragma unroll
                for (int j = 0; j < 8; j++) acc[i][j] += a[i] * b[j];
        }
        __syncthreads();
    }
    #pragma unroll
    for (int i = 0; i < 8; i++) {
        int ml = (i < 4) ? (ty * 4 + i) : (64 + ty * 4 + i - 4);
        int m = m_base + ml;
        if (m >= M) continue;
        size_t crow;
        if (cmode == 0) crow = (size_t)m;
        else { int bb = m / DEC_T, tt = m - bb * DEC_T; crow = (size_t)bb * SRC_T + tt + 1; }
        float* crp = C + crow * (size_t)N;
        #pragma unroll
        for (int jg = 0; jg < 2; jg++) {
            int n = n_base + jg * 64 + tx * 4;
            if (n < N) {
                float4 v;
                v.x = acc[i][jg * 4 + 0] + bias[n + 0];
                v.y = acc[i][jg * 4 + 1] + bias[n + 1];
                v.z = acc[i][jg * 4 + 2] + bias[n + 2];
                v.w = acc[i][jg * 4 + 3] + bias[n + 3];
                *(float4*)(crp + n) = v;
            }
        }
    }
}

// ---------------- persistent GRU layer recurrence ----------------
// Per step t: phase A computes gh partials (K split 8x64, N split 16x96),
// barrier, phase B fuses partial reduction + gates + state update, barrier.
// Weight tile (64x96 slice of WhhT) is loop-invariant: loaded into smem ONCE.
__global__ void __launch_bounds__(256) gru_layer_kernel(
    const float* __restrict__ gi, const float* __restrict__ WhhT,
    const float* __restrict__ bhh, const float* __restrict__ hinit,
    float* __restrict__ Y, float* __restrict__ hfinal, int T) {
    __shared__ float sh_hT[64][65];   // [k][m]  (65-stride: conflict-free stores; scalar reads)
    __shared__ float sh_w[64][96];    // [k][n]  loop-invariant weight tile
    int blk = blockIdx.x, tid = threadIdx.x;

    for (int e = blk * 256 + tid; e < BATCH * HID; e += RBLK * 256)
        g_h[e] = hinit ? hinit[e] : 0.0f;

    const int kc = blk >> 4, nt = blk & 15;
    const int k0 = kc * 64, n0 = nt * 96;
    const int tx = tid & 15, ty = tid >> 4;   // tx: 6-wide n, ty: 4-wide m

    // load weight tile once (invariant across all T steps)
    #pragma unroll
    for (int r = 0; r < 24; ++r) {
        int idx = r * 256 + tid;
        int k = idx / 96, n = idx - k * 96;
        sh_w[k][n] = WhhT[(size_t)(k0 + k) * G3 + n0 + n];
    }
    gbar();

    for (int t = 0; t < T; ++t) {
        // ---- phase A: partial gh = h[:, k0:k0+64] @ WhhT[k0:k0+64, n0:n0+96]
        #pragma unroll
        for (int r = 0; r < 16; ++r) {
            int idx = r * 256 + tid;
            int m = idx >> 6, k = idx & 63;
            sh_hT[k][m] = g_h[m * HID + k0 + k];
        }
        __syncthreads();
        float acc[4][6] = {};
        #pragma unroll
        for (int k = 0; k < 64; ++k) {
            float am[4], bb[6];
            #pragma unroll
            for (int i = 0; i < 4; i++) am[i] = sh_hT[k][ty * 4 + i];  // scalar LDS (65-stride row is not 16B-aligned)
            #pragma unroll
            for (int j = 0; j < 6; j++) bb[j] = sh_w[k][tx * 6 + j];
            #pragma unroll
            for (int i = 0; i < 4; i++)
                #pragma unroll
                for (int j = 0; j < 6; j++) acc[i][j] += am[i] * bb[j];
        }
        #pragma unroll
        for (int i = 0; i < 4; i++) {
            int m = ty * 4 + i;
            float* dst = &g_ghp[kc][m * G3 + n0 + tx * 6];
            #pragma unroll
            for (int j = 0; j < 6; j++) dst[j] = acc[i][j];
        }
        gbar();
        // ---- phase B: gates + state update (one thread per (b, j))
        {
            int e = blk * 256 + tid;            // 0..32767 exactly
            int b = e >> 9, j = e & 511;
            const float* gir = gi + ((size_t)b * T + t) * G3;
            float s0 = 0.f, s1 = 0.f, s2 = 0.f;
            #pragma unroll
            for (int c = 0; c < 8; c++) {
                const float* p = &g_ghp[c][b * G3];
                s0 += p[j]; s1 += p[512 + j]; s2 += p[1024 + j];
            }
            float hv = g_h[e];
            float r = 1.f / (1.f + __expf(-(gir[j]        + s0 + bhh[j])));
            float z = 1.f / (1.f + __expf(-(gir[512 + j]  + s1 + bhh[512 + j])));
            float nn = tanhf(gir[1024 + j] + r * (s2 + bhh[1024 + j]));
            float hn = (1.f - z) * nn + z * hv;
            Y[((size_t)b * T + t) * HID + j] = hn;
            g_h[e] = hn;
        }
        gbar();
    }
    for (int e = blk * 256 + tid; e < BATCH * HID; e += RBLK * 256)
        hfinal[e] = g_h[e];
}

// ---------------- zero t=0 output plane ----------------
__global__ void zero_t0_kernel(float* __restrict__ out) {
    int idx = blockIdx.x * 256 + threadIdx.x;
    if (idx < BATCH * VOCAB) {
        int b = idx / VOCAB, v = idx - b * VOCAB;
        out[(size_t)b * SRC_T * VOCAB + v] = 0.0f;
    }
}

// ---------------- host driver ----------------
extern "C" void kernel_launch(void* const* d_in, const int* in_sizes, int n_in,
                              void* d_out, int out_size) {
    const int*   src     = (const int*)  d_in[0];
    const int*   trg     = (const int*)  d_in[1];
    const float* enc_emb = (const float*)d_in[2];
    const float* enc_Wih = (const float*)d_in[3];
    const float* enc_Whh = (const float*)d_in[4];
    const float* enc_bih = (const float*)d_in[5];
    const float* enc_bhh = (const float*)d_in[6];
    const float* dec_emb = (const float*)d_in[7];
    const float* dec_Wih = (const float*)d_in[8];
    const float* dec_Whh = (const float*)d_in[9];
    const float* dec_bih = (const float*)d_in[10];
    const float* dec_bhh = (const float*)d_in[11];
    const float* fc_W    = (const float*)d_in[12];
    const float* fc_b    = (const float*)d_in[13];
    float* out = (float*)d_out;

    float *pX, *pY, *pgi, *pWTih, *pWThh, *pfcT, *phenc, *phdec;
    cudaGetSymbolAddress((void**)&pX,    g_X);
    cudaGetSymbolAddress((void**)&pY,    g_Ybuf);
    cudaGetSymbolAddress((void**)&pgi,   g_gi);
    cudaGetSymbolAddress((void**)&pWTih, g_WTih);
    cudaGetSymbolAddress((void**)&pWThh, g_WThh);
    cudaGetSymbolAddress((void**)&pfcT,  g_fcT);
    cudaGetSymbolAddress((void**)&phenc, g_hid_enc);
    cudaGetSymbolAddress((void**)&phdec, g_hid_dec);

    dim3 tb(32, 8);
    dim3 tW(EMB / 32, G3 / 32);          // transpose grids for Wih/Whh (1536x512)

    // ----- encoder -----
    embed_kernel<<<BATCH * SRC_T, 128>>>(src, SRC_T, enc_emb, pX, SRC_T);
    for (int l = 0; l < NLAYERS; l++) {
        transpose_kernel<<<tW, tb>>>(enc_Wih + (size_t)l * G3 * EMB, pWTih, G3, EMB);
        transpose_kernel<<<tW, tb>>>(enc_Whh + (size_t)l * G3 * HID, pWThh, G3, HID);
        const float* Ain = (l == 0) ? pX : pY;
        float*       Yout = (l == 0) ? pY : pX;
        sgemm_bias<<<dim3(G3 / 128, (BATCH * SRC_T + 127) / 128), 256>>>(
            Ain, pWTih, pgi, enc_bih + l * G3, BATCH * SRC_T, G3, EMB, 0);
        gru_layer_kernel<<<RBLK, 256>>>(pgi, pWThh, enc_bhh + l * G3, nullptr,
                                        Yout, phenc + l * BATCH * HID, SRC_T);
    }

    // ----- decoder -----
    embed_kernel<<<BATCH * DEC_T, 128>>>(trg, SRC_T, dec_emb, pX, DEC_T);
    const int MD = BATCH * DEC_T;   // 8128
    for (int l = 0; l < NLAYERS; l++) {
        transpose_kernel<<<tW, tb>>>(dec_Wih + (size_t)l * G3 * EMB, pWTih, G3, EMB);
        transpose_kernel<<<tW, tb>>>(dec_Whh + (size_t)l * G3 * HID, pWThh, G3, HID);
        const float* Ain = (l == 0) ? pX : pY;
        float*       Yout = (l == 0) ? pY : pX;
        sgemm_bias<<<dim3(G3 / 128, (MD + 127) / 128), 256>>>(
            Ain, pWTih, pgi, dec_bih + l * G3, MD, G3, EMB, 0);
        gru_layer_kernel<<<RBLK, 256>>>(pgi, pWThh, dec_bhh + l * G3,
                                        phenc + l * BATCH * HID,
                                        Yout, phdec + l * BATCH * HID, DEC_T);
    }

    // ----- output head -----
    zero_t0_kernel<<<(BATCH * VOCAB + 255) / 256, 256>>>(out);
    transpose_kernel<<<dim3(HID / 32, (VOCAB + 31) / 32), tb>>>(fc_W, pfcT, VOCAB, HID);
    sgemm_bias<<<dim3((VOCAB + 127) / 128, (MD + 127) / 128), 256>>>(
        pX, pfcT, out, fc_b, MD, VOCAB, HID, 1);
}

// round 5
// speedup vs baseline: 1.0848x; 1.0848x over previous
#include <cuda_runtime.h>
#include <cstddef>

#define BATCH   64
#define SRC_T   128
#define DEC_T   127
#define EMB     512
#define HID     512
#define G3      1536
#define VOCAB   10000
#define NLAYERS 2
#define RBLK    128   // persistent recurrence blocks (<= 148 SMs, guaranteed co-resident)

// ---------------- scratch (device globals; no runtime allocation) ----------------
__device__ float g_X   [BATCH*SRC_T*EMB];     // ping
__device__ float g_Ybuf[BATCH*SRC_T*EMB];     // pong
__device__ float g_gi  [BATCH*SRC_T*G3];      // precomputed input gates
__device__ float g_WTih[EMB*G3];              // transposed Wih of current layer
__device__ float g_WThh[HID*G3];              // transposed Whh of current layer
__device__ float g_fcT [HID*VOCAB];           // transposed fc_W
__device__ float g_h   [BATCH*HID];           // recurrent state
__device__ float g_hid_enc[NLAYERS*BATCH*HID];
__device__ float g_hid_dec[NLAYERS*BATCH*HID];
__device__ float g_ghp [8][BATCH*G3];         // K-split partial sums of h@WhhT
__device__ unsigned g_bar_count;
__device__ unsigned g_bar_gen;

// ---------------- grid barrier (all RBLK blocks resident) ----------------
// Arrive: one atomicAdd per block. Wait: VOLATILE LOAD poll (plain L2 reads to
// one line do NOT serialize in the LTS atomic ALU the way RMW polling does).
// __threadfence (gpu scope) after passing emits CCTL.IVALL -> post-barrier
// plain loads observe other blocks' writes.
__device__ __forceinline__ void gbar() {
    __syncthreads();
    if (threadIdx.x == 0) {
        unsigned gen = *(volatile unsigned*)&g_bar_gen;  // stable until release (needs our arrival)
        __threadfence();                                  // make our prior writes visible
        if (atomicAdd(&g_bar_count, 1u) == RBLK - 1u) {
            atomicExch(&g_bar_count, 0u);
            __threadfence();
            atomicExch(&g_bar_gen, gen + 1u);
        } else {
            while (*(volatile unsigned*)&g_bar_gen == gen) { }
        }
        __threadfence();
    }
    __syncthreads();
}

// ---------------- embedding gather ----------------
__global__ void embed_kernel(const int* __restrict__ tok, int tokStride,
                             const float* __restrict__ emb,
                             float* __restrict__ X, int T) {
    int m = blockIdx.x;
    int b = m / T, t = m - b * T;
    int v = tok[b * tokStride + t];
    const float4* s = (const float4*)(emb + (size_t)v * EMB);
    float4* d = (float4*)(X + (size_t)m * EMB);
    d[threadIdx.x] = s[threadIdx.x];
}

// ---------------- transpose: D[C][R] = S[R][C] ----------------
__global__ void transpose_kernel(const float* __restrict__ S, float* __restrict__ D,
                                 int R, int C) {
    __shared__ float tile[32][33];
    int c0 = blockIdx.x * 32, r0 = blockIdx.y * 32;
    int x = threadIdx.x, y = threadIdx.y;
    #pragma unroll
    for (int i = 0; i < 32; i += 8) {
        int r = r0 + y + i, c = c0 + x;
        if (r < R && c < C) tile[y + i][x] = S[(size_t)r * C + c];
    }
    __syncthreads();
    #pragma unroll
    for (int i = 0; i < 32; i += 8) {
        int c = c0 + y + i, r = r0 + x;
        if (r < R && c < C) D[(size_t)c * R + r] = tile[x][y + i];
    }
}

// ---------------- fp32 SGEMM: C[M,N] = A[M,K] @ Bm[K,N] + bias[N] ----------------
// cmode 0: C row = m.  cmode 1 (FC head): m = b*127+t -> C row = b*128 + t + 1.
__global__ void __launch_bounds__(256) sgemm_bias(
    const float* __restrict__ A, const float* __restrict__ Bm,
    float* __restrict__ C, const float* __restrict__ bias,
    int M, int N, int K, int cmode) {
    const int BM = 128, BN = 128, BK = 8;
    __shared__ float As[BK][BM];
    __shared__ float Bs[BK][BN];
    int tid = threadIdx.x;
    int tx = tid & 15, ty = tid >> 4;
    int m_base = blockIdx.y * BM, n_base = blockIdx.x * BN;
    int arow = tid >> 1, acol = (tid & 1) * 4;
    int brow = tid >> 5, bcol = (tid & 31) * 4;
    float acc[8][8] = {};
    for (int k0 = 0; k0 < K; k0 += BK) {
        float4 av = make_float4(0.f, 0.f, 0.f, 0.f);
        int am = m_base + arow;
        if (am < M) av = *(const float4*)(A + (size_t)am * K + k0 + acol);
        As[acol + 0][arow] = av.x; As[acol + 1][arow] = av.y;
        As[acol + 2][arow] = av.z; As[acol + 3][arow] = av.w;
        float4 bv = make_float4(0.f, 0.f, 0.f, 0.f);
        int bn = n_base + bcol;
        if (bn < N) bv = *(const float4*)(Bm + (size_t)(k0 + brow) * N + bn);
        *(float4*)&Bs[brow][bcol] = bv;
        __syncthreads();
        #pragma unroll
        for (int k = 0; k < BK; k++) {
            float a[8], b[8];
            #pragma unroll
            for (int i = 0; i < 4; i++) {
                a[i]     = As[k][ty * 4 + i];
                a[4 + i] = As[k][64 + ty * 4 + i];
                b[i]     = Bs[k][tx * 4 + i];
                b[4 + i] = Bs[k][64 + tx * 4 + i];
            }
            #pragma unroll
            for (int i = 0; i < 8; i++)
                #pragma unroll
                for (int j = 0; j < 8; j++) acc[i][j] += a[i] * b[j];
        }
        __syncthreads();
    }
    #pragma unroll
    for (int i = 0; i < 8; i++) {
        int ml = (i < 4) ? (ty * 4 + i) : (64 + ty * 4 + i - 4);
        int m = m_base + ml;
        if (m >= M) continue;
        size_t crow;
        if (cmode == 0) crow = (size_t)m;
        else { int bb = m / DEC_T, tt = m - bb * DEC_T; crow = (size_t)bb * SRC_T + tt + 1; }
        float* crp = C + crow * (size_t)N;
        #pragma unroll
        for (int jg = 0; jg < 2; jg++) {
            int n = n_base + jg * 64 + tx * 4;
            if (n < N) {
                float4 v;
                v.x = acc[i][jg * 4 + 0] + bias[n + 0];
                v.y = acc[i][jg * 4 + 1] + bias[n + 1];
                v.z = acc[i][jg * 4 + 2] + bias[n + 2];
                v.w = acc[i][jg * 4 + 3] + bias[n + 3];
                *(float4*)(crp + n) = v;
            }
        }
    }
}

// ---------------- persistent GRU layer recurrence ----------------
// Per step t: phase A computes gh partials (K split 8x64, N split 16x96),
// barrier, phase B fuses partial reduction + gates + state update, barrier.
// Weight tile in smem once; bhh biases + own h element in registers for all T.
__global__ void __launch_bounds__(256) gru_layer_kernel(
    const float* __restrict__ gi, const float* __restrict__ WhhT,
    const float* __restrict__ bhh, const float* __restrict__ hinit,
    float* __restrict__ Y, float* __restrict__ hfinal, int T) {
    __shared__ float sh_hT[64][65];   // [k][m]  (65-stride: conflict-free stores; scalar reads)
    __shared__ float sh_w[64][96];    // [k][n]  loop-invariant weight tile
    int blk = blockIdx.x, tid = threadIdx.x;

    // this thread owns exactly one state element e (RBLK*256 == BATCH*HID)
    const int e = blk * 256 + tid;
    const int b = e >> 9, j = e & 511;
    float hreg = hinit ? hinit[e] : 0.0f;
    g_h[e] = hreg;

    // loop-invariant gate biases in registers
    const float bh_r = bhh[j];
    const float bh_z = bhh[512 + j];
    const float bh_n = bhh[1024 + j];

    const int kc = blk >> 4, nt = blk & 15;
    const int k0 = kc * 64, n0 = nt * 96;
    const int tx = tid & 15, ty = tid >> 4;   // tx: 6-wide n, ty: 4-wide m

    // load weight tile once (invariant across all T steps)
    #pragma unroll
    for (int r = 0; r < 24; ++r) {
        int idx = r * 256 + tid;
        int k = idx / 96, n = idx - k * 96;
        sh_w[k][n] = WhhT[(size_t)(k0 + k) * G3 + n0 + n];
    }
    gbar();

    for (int t = 0; t < T; ++t) {
        // prefetch this step's input-gate values (independent of phase A)
        const float* gir = gi + ((size_t)b * T + t) * G3;
        float gi_r = __ldg(gir + j);
        float gi_z = __ldg(gir + 512 + j);
        float gi_n = __ldg(gir + 1024 + j);

        // ---- phase A: partial gh = h[:, k0:k0+64] @ WhhT[k0:k0+64, n0:n0+96]
        #pragma unroll
        for (int r = 0; r < 16; ++r) {
            int idx = r * 256 + tid;
            int m = idx >> 6, k = idx & 63;
            sh_hT[k][m] = g_h[m * HID + k0 + k];
        }
        __syncthreads();
        float acc[4][6] = {};
        #pragma unroll
        for (int k = 0; k < 64; ++k) {
            float am[4], bb[6];
            #pragma unroll
            for (int i = 0; i < 4; i++) am[i] = sh_hT[k][ty * 4 + i];
            #pragma unroll
            for (int jn = 0; jn < 6; jn++) bb[jn] = sh_w[k][tx * 6 + jn];
            #pragma unroll
            for (int i = 0; i < 4; i++)
                #pragma unroll
                for (int jn = 0; jn < 6; jn++) acc[i][jn] += am[i] * bb[jn];
        }
        #pragma unroll
        for (int i = 0; i < 4; i++) {
            int m = ty * 4 + i;
            float* dst = &g_ghp[kc][m * G3 + n0 + tx * 6];
            #pragma unroll
            for (int jn = 0; jn < 6; jn++) dst[jn] = acc[i][jn];
        }
        gbar();
        // ---- phase B: gates + state update (one thread per (b, j))
        {
            float s0 = 0.f, s1 = 0.f, s2 = 0.f;
            #pragma unroll
            for (int c = 0; c < 8; c++) {
                const float* p = &g_ghp[c][b * G3];
                s0 += p[j]; s1 += p[512 + j]; s2 += p[1024 + j];
            }
            float r = 1.f / (1.f + __expf(-(gi_r + s0 + bh_r)));
            float z = 1.f / (1.f + __expf(-(gi_z + s1 + bh_z)));
            float nn = tanhf(gi_n + r * (s2 + bh_n));
            float hn = (1.f - z) * nn + z * hreg;
            Y[((size_t)b * T + t) * HID + j] = hn;
            g_h[e] = hn;
            hreg = hn;
        }
        gbar();
    }
    hfinal[e] = hreg;
}

// ---------------- zero t=0 output plane ----------------
__global__ void zero_t0_kernel(float* __restrict__ out) {
    int idx = blockIdx.x * 256 + threadIdx.x;
    if (idx < BATCH * VOCAB) {
        int b = idx / VOCAB, v = idx - b * VOCAB;
        out[(size_t)b * SRC_T * VOCAB + v] = 0.0f;
    }
}

// ---------------- host driver ----------------
extern "C" void kernel_launch(void* const* d_in, const int* in_sizes, int n_in,
                              void* d_out, int out_size) {
    const int*   src     = (const int*)  d_in[0];
    const int*   trg     = (const int*)  d_in[1];
    const float* enc_emb = (const float*)d_in[2];
    const float* enc_Wih = (const float*)d_in[3];
    const float* enc_Whh = (const float*)d_in[4];
    const float* enc_bih = (const float*)d_in[5];
    const float* enc_bhh = (const float*)d_in[6];
    const float* dec_emb = (const float*)d_in[7];
    const float* dec_Wih = (const float*)d_in[8];
    const float* dec_Whh = (const float*)d_in[9];
    const float* dec_bih = (const float*)d_in[10];
    const float* dec_bhh = (const float*)d_in[11];
    const float* fc_W    = (const float*)d_in[12];
    const float* fc_b    = (const float*)d_in[13];
    float* out = (float*)d_out;

    float *pX, *pY, *pgi, *pWTih, *pWThh, *pfcT, *phenc, *phdec;
    cudaGetSymbolAddress((void**)&pX,    g_X);
    cudaGetSymbolAddress((void**)&pY,    g_Ybuf);
    cudaGetSymbolAddress((void**)&pgi,   g_gi);
    cudaGetSymbolAddress((void**)&pWTih, g_WTih);
    cudaGetSymbolAddress((void**)&pWThh, g_WThh);
    cudaGetSymbolAddress((void**)&pfcT,  g_fcT);
    cudaGetSymbolAddress((void**)&phenc, g_hid_enc);
    cudaGetSymbolAddress((void**)&phdec, g_hid_dec);

    dim3 tb(32, 8);
    dim3 tW(EMB / 32, G3 / 32);          // transpose grids for Wih/Whh (1536x512)

    // ----- encoder -----
    embed_kernel<<<BATCH * SRC_T, 128>>>(src, SRC_T, enc_emb, pX, SRC_T);
    for (int l = 0; l < NLAYERS; l++) {
        transpose_kernel<<<tW, tb>>>(enc_Wih + (size_t)l * G3 * EMB, pWTih, G3, EMB);
        transpose_kernel<<<tW, tb>>>(enc_Whh + (size_t)l * G3 * HID, pWThh, G3, HID);
        const float* Ain = (l == 0) ? pX : pY;
        float*       Yout = (l == 0) ? pY : pX;
        sgemm_bias<<<dim3(G3 / 128, (BATCH * SRC_T + 127) / 128), 256>>>(
            Ain, pWTih, pgi, enc_bih + l * G3, BATCH * SRC_T, G3, EMB, 0);
        gru_layer_kernel<<<RBLK, 256>>>(pgi, pWThh, enc_bhh + l * G3, nullptr,
                                        Yout, phenc + l * BATCH * HID, SRC_T);
    }

    // ----- decoder -----
    embed_kernel<<<BATCH * DEC_T, 128>>>(trg, SRC_T, dec_emb, pX, DEC_T);
    const int MD = BATCH * DEC_T;   // 8128
    for (int l = 0; l < NLAYERS; l++) {
        transpose_kernel<<<tW, tb>>>(dec_Wih + (size_t)l * G3 * EMB, pWTih, G3, EMB);
        transpose_kernel<<<tW, tb>>>(dec_Whh + (size_t)l * G3 * HID, pWThh, G3, HID);
        const float* Ain = (l == 0) ? pX : pY;
        float*       Yout = (l == 0) ? pY : pX;
        sgemm_bias<<<dim3(G3 / 128, (MD + 127) / 128), 256>>>(
            Ain, pWTih, pgi, dec_bih + l * G3, MD, G3, EMB, 0);
        gru_layer_kernel<<<RBLK, 256>>>(pgi, pWThh, dec_bhh + l * G3,
                                        phenc + l * BATCH * HID,
                                        Yout, phdec + l * BATCH * HID, DEC_T);
    }

    // ----- output head -----
    zero_t0_kernel<<<(BATCH * VOCAB + 255) / 256, 256>>>(out);
    transpose_kernel<<<dim3(HID / 32, (VOCAB + 31) / 32), tb>>>(fc_W, pfcT, VOCAB, HID);
    sgemm_bias<<<dim3((VOCAB + 127) / 128, (MD + 127) / 128), 256>>>(
        pX, pfcT, out, fc_b, MD, VOCAB, HID, 1);
}

// round 6
// speedup vs baseline: 1.1888x; 1.0959x over previous
#include <cuda_runtime.h>
#include <cstddef>

#define BATCH   64
#define SRC_T   128
#define DEC_T   127
#define EMB     512
#define HID     512
#define G3      1536
#define VOCAB   10000
#define NLAYERS 2
#define RBLK    128   // persistent recurrence blocks (<= 148 SMs, guaranteed co-resident)

// ---------------- scratch (device globals; no runtime allocation) ----------------
__device__ float g_X   [BATCH*SRC_T*EMB];     // ping
__device__ float g_Ybuf[BATCH*SRC_T*EMB];     // pong
__device__ float g_gi  [BATCH*SRC_T*G3];      // precomputed input gates
__device__ float g_WTih[EMB*G3];              // transposed Wih of current layer
__device__ float g_WThh[HID*G3];              // transposed Whh of current layer
__device__ float g_fcT [HID*VOCAB];           // transposed fc_W
__device__ float g_h   [BATCH*HID];           // recurrent state (cg access only)
__device__ float g_hid_enc[NLAYERS*BATCH*HID];
__device__ float g_hid_dec[NLAYERS*BATCH*HID];
__device__ float g_ghp [8][BATCH*G3];         // K-split partial sums (cg access only)
__device__ unsigned g_bar_count;
__device__ unsigned g_bar_gen;

// ---------------- memory-model primitives ----------------
__device__ __forceinline__ unsigned ld_relaxed_u32(const unsigned* p) {
    unsigned v;
    asm volatile("ld.relaxed.gpu.global.u32 %0, [%1];" : "=r"(v) : "l"(p) : "memory");
    return v;
}
__device__ __forceinline__ unsigned ld_acquire_u32(const unsigned* p) {
    unsigned v;
    asm volatile("ld.acquire.gpu.global.u32 %0, [%1];" : "=r"(v) : "l"(p) : "memory");
    return v;
}
__device__ __forceinline__ void st_relaxed_u32(unsigned* p, unsigned v) {
    asm volatile("st.relaxed.gpu.global.u32 [%0], %1;" :: "l"(p), "r"(v) : "memory");
}
__device__ __forceinline__ void st_release_u32(unsigned* p, unsigned v) {
    asm volatile("st.release.gpu.global.u32 [%0], %1;" :: "l"(p), "r"(v) : "memory");
}
__device__ __forceinline__ unsigned atom_add_release(unsigned* p, unsigned v) {
    unsigned o;
    asm volatile("atom.release.gpu.global.add.u32 %0, [%1], %2;"
                 : "=r"(o) : "l"(p), "r"(v) : "memory");
    return o;
}
// L1-bypassing (L2-coherent) data accessors for cross-block traffic.
__device__ __forceinline__ float ld_cg(const float* p) {
    float v; asm volatile("ld.global.cg.f32 %0, [%1];" : "=f"(v) : "l"(p)); return v;
}
__device__ __forceinline__ void st_cg(float* p, float v) {
    asm volatile("st.global.cg.f32 [%0], %1;" :: "l"(p), "f"(v));
}

// ---------------- grid barrier: acquire/release, NO full fences, NO L1 flush ----
// Cross-block data uses .cg (L2-only), so no CCTL.IVALL is needed anywhere.
// Arrive: atom.add.release (orders this block's prior .cg stores).
// Wait:   ld.acquire poll of generation (orders subsequent .cg loads).
__device__ __forceinline__ void gbar() {
    __syncthreads();
    if (threadIdx.x == 0) {
        unsigned gen = ld_relaxed_u32(&g_bar_gen);   // stable until our own arrival
        if (atom_add_release(&g_bar_count, 1u) == RBLK - 1u) {
            st_relaxed_u32(&g_bar_count, 0u);        // ordered before release below
            st_release_u32(&g_bar_gen, gen + 1u);
        } else {
            while (ld_acquire_u32(&g_bar_gen) == gen) { }
        }
    }
    __syncthreads();
}

// ---------------- embedding gather ----------------
__global__ void embed_kernel(const int* __restrict__ tok, int tokStride,
                             const float* __restrict__ emb,
                             float* __restrict__ X, int T) {
    int m = blockIdx.x;
    int b = m / T, t = m - b * T;
    int v = tok[b * tokStride + t];
    const float4* s = (const float4*)(emb + (size_t)v * EMB);
    float4* d = (float4*)(X + (size_t)m * EMB);
    d[threadIdx.x] = s[threadIdx.x];
}

// ---------------- transpose: D[C][R] = S[R][C] ----------------
__global__ void transpose_kernel(const float* __restrict__ S, float* __restrict__ D,
                                 int R, int C) {
    __shared__ float tile[32][33];
    int c0 = blockIdx.x * 32, r0 = blockIdx.y * 32;
    int x = threadIdx.x, y = threadIdx.y;
    #pragma unroll
    for (int i = 0; i < 32; i += 8) {
        int r = r0 + y + i, c = c0 + x;
        if (r < R && c < C) tile[y + i][x] = S[(size_t)r * C + c];
    }
    __syncthreads();
    #pragma unroll
    for (int i = 0; i < 32; i += 8) {
        int c = c0 + y + i, r = r0 + x;
        if (r < R && c < C) D[(size_t)c * R + r] = tile[x][y + i];
    }
}

// ---------------- fp32 SGEMM: C[M,N] = A[M,K] @ Bm[K,N] + bias[N] ----------------
// cmode 0: C row = m.  cmode 1 (FC head): m = b*127+t -> C row = b*128 + t + 1.
__global__ void __launch_bounds__(256) sgemm_bias(
    const float* __restrict__ A, const float* __restrict__ Bm,
    float* __restrict__ C, const float* __restrict__ bias,
    int M, int N, int K, int cmode) {
    const int BM = 128, BN = 128, BK = 8;
    __shared__ float As[BK][BM];
    __shared__ float Bs[BK][BN];
    int tid = threadIdx.x;
    int tx = tid & 15, ty = tid >> 4;
    int m_base = blockIdx.y * BM, n_base = blockIdx.x * BN;
    int arow = tid >> 1, acol = (tid & 1) * 4;
    int brow = tid >> 5, bcol = (tid & 31) * 4;
    float acc[8][8] = {};
    for (int k0 = 0; k0 < K; k0 += BK) {
        float4 av = make_float4(0.f, 0.f, 0.f, 0.f);
        int am = m_base + arow;
        if (am < M) av = *(const float4*)(A + (size_t)am * K + k0 + acol);
        As[acol + 0][arow] = av.x; As[acol + 1][arow] = av.y;
        As[acol + 2][arow] = av.z; As[acol + 3][arow] = av.w;
        float4 bv = make_float4(0.f, 0.f, 0.f, 0.f);
        int bn = n_base + bcol;
        if (bn < N) bv = *(const float4*)(Bm + (size_t)(k0 + brow) * N + bn);
        *(float4*)&Bs[brow][bcol] = bv;
        __syncthreads();
        #pragma unroll
        for (int k = 0; k < BK; k++) {
            float a[8], b[8];
            #pragma unroll
            for (int i = 0; i < 4; i++) {
                a[i]     = As[k][ty * 4 + i];
                a[4 + i] = As[k][64 + ty * 4 + i];
                b[i]     = Bs[k][tx * 4 + i];
                b[4 + i] = Bs[k][64 + tx * 4 + i];
            }
            #pragma unroll
            for (int i = 0; i < 8; i++)
                #pragma unroll
                for (int j = 0; j < 8; j++) acc[i][j] += a[i] * b[j];
        }
        __syncthreads();
    }
    #pragma unroll
    for (int i = 0; i < 8; i++) {
        int ml = (i < 4) ? (ty * 4 + i) : (64 + ty * 4 + i - 4);
        int m = m_base + ml;
        if (m >= M) continue;
        size_t crow;
        if (cmode == 0) crow = (size_t)m;
        else { int bb = m / DEC_T, tt = m - bb * DEC_T; crow = (size_t)bb * SRC_T + tt + 1; }
        float* crp = C + crow * (size_t)N;
        #pragma unroll
        for (int jg = 0; jg < 2; jg++) {
            int n = n_base + jg * 64 + tx * 4;
            if (n < N) {
                float4 v;
                v.x = acc[i][jg * 4 + 0] + bias[n + 0];
                v.y = acc[i][jg * 4 + 1] + bias[n + 1];
                v.z = acc[i][jg * 4 + 2] + bias[n + 2];
                v.w = acc[i][jg * 4 + 3] + bias[n + 3];
                *(float4*)(crp + n) = v;
            }
        }
    }
}

// ---------------- persistent GRU layer recurrence ----------------
// Per step t: phase A computes gh partials (K split 8x64, N split 16x96),
// barrier, phase B fuses partial reduction + gates + state update, barrier.
// All cross-block data via .cg (L2); barriers via acquire/release (no fences).
__global__ void __launch_bounds__(256) gru_layer_kernel(
    const float* __restrict__ gi, const float* __restrict__ WhhT,
    const float* __restrict__ bhh, const float* __restrict__ hinit,
    float* __restrict__ Y, float* __restrict__ hfinal, int T) {
    __shared__ float sh_hT[64][65];   // [k][m]  (65-stride: conflict-free stores; scalar reads)
    __shared__ float sh_w[64][96];    // [k][n]  loop-invariant weight tile
    int blk = blockIdx.x, tid = threadIdx.x;

    // this thread owns exactly one state element e (RBLK*256 == BATCH*HID)
    const int e = blk * 256 + tid;
    const int b = e >> 9, j = e & 511;
    float hreg = hinit ? hinit[e] : 0.0f;
    st_cg(&g_h[e], hreg);

    // loop-invariant gate biases in registers
    const float bh_r = bhh[j];
    const float bh_z = bhh[512 + j];
    const float bh_n = bhh[1024 + j];

    const int kc = blk >> 4, nt = blk & 15;
    const int k0 = kc * 64, n0 = nt * 96;
    const int tx = tid & 15, ty = tid >> 4;   // tx: 6-wide n, ty: 4-wide m

    // load weight tile once (invariant across all T steps)
    #pragma unroll
    for (int r = 0; r < 24; ++r) {
        int idx = r * 256 + tid;
        int k = idx / 96, n = idx - k * 96;
        sh_w[k][n] = WhhT[(size_t)(k0 + k) * G3 + n0 + n];
    }
    gbar();

    for (int t = 0; t < T; ++t) {
        // prefetch this step's input-gate values (kernel-constant data; plain loads)
        const float* gir = gi + ((size_t)b * T + t) * G3;
        float gi_r = __ldg(gir + j);
        float gi_z = __ldg(gir + 512 + j);
        float gi_n = __ldg(gir + 1024 + j);

        // ---- phase A: partial gh = h[:, k0:k0+64] @ WhhT[k0:k0+64, n0:n0+96]
        #pragma unroll
        for (int r = 0; r < 16; ++r) {
            int idx = r * 256 + tid;
            int m = idx >> 6, k = idx & 63;
            sh_hT[k][m] = ld_cg(&g_h[m * HID + k0 + k]);
        }
        __syncthreads();
        float acc[4][6] = {};
        #pragma unroll
        for (int k = 0; k < 64; ++k) {
            float am[4], bb[6];
            #pragma unroll
            for (int i = 0; i < 4; i++) am[i] = sh_hT[k][ty * 4 + i];
            #pragma unroll
            for (int jn = 0; jn < 6; jn++) bb[jn] = sh_w[k][tx * 6 + jn];
            #pragma unroll
            for (int i = 0; i < 4; i++)
                #pragma unroll
                for (int jn = 0; jn < 6; jn++) acc[i][jn] += am[i] * bb[jn];
        }
        #pragma unroll
        for (int i = 0; i < 4; i++) {
            int m = ty * 4 + i;
            float* dst = &g_ghp[kc][m * G3 + n0 + tx * 6];
            #pragma unroll
            for (int jn = 0; jn < 6; jn++) st_cg(dst + jn, acc[i][jn]);
        }
        gbar();
        // ---- phase B: gates + state update (one thread per (b, j))
        {
            float s0 = 0.f, s1 = 0.f, s2 = 0.f;
            #pragma unroll
            for (int c = 0; c < 8; c++) {
                const float* p = &g_ghp[c][b * G3];
                s0 += ld_cg(p + j);
                s1 += ld_cg(p + 512 + j);
                s2 += ld_cg(p + 1024 + j);
            }
            float r = 1.f / (1.f + __expf(-(gi_r + s0 + bh_r)));
            float z = 1.f / (1.f + __expf(-(gi_z + s1 + bh_z)));
            float nn = tanhf(gi_n + r * (s2 + bh_n));
            float hn = (1.f - z) * nn + z * hreg;
            Y[((size_t)b * T + t) * HID + j] = hn;   // consumed by later kernels only
            st_cg(&g_h[e], hn);
            hreg = hn;
        }
        gbar();
    }
    hfinal[e] = hreg;
}

// ---------------- zero t=0 output plane ----------------
__global__ void zero_t0_kernel(float* __restrict__ out) {
    int idx = blockIdx.x * 256 + threadIdx.x;
    if (idx < BATCH * VOCAB) {
        int b = idx / VOCAB, v = idx - b * VOCAB;
        out[(size_t)b * SRC_T * VOCAB + v] = 0.0f;
    }
}

// ---------------- host driver ----------------
extern "C" void kernel_launch(void* const* d_in, const int* in_sizes, int n_in,
                              void* d_out, int out_size) {
    const int*   src     = (const int*)  d_in[0];
    const int*   trg     = (const int*)  d_in[1];
    const float* enc_emb = (const float*)d_in[2];
    const float* enc_Wih = (const float*)d_in[3];
    const float* enc_Whh = (const float*)d_in[4];
    const float* enc_bih = (const float*)d_in[5];
    const float* enc_bhh = (const float*)d_in[6];
    const float* dec_emb = (const float*)d_in[7];
    const float* dec_Wih = (const float*)d_in[8];
    const float* dec_Whh = (const float*)d_in[9];
    const float* dec_bih = (const float*)d_in[10];
    const float* dec_bhh = (const float*)d_in[11];
    const float* fc_W    = (const float*)d_in[12];
    const float* fc_b    = (const float*)d_in[13];
    float* out = (float*)d_out;

    float *pX, *pY, *pgi, *pWTih, *pWThh, *pfcT, *phenc, *phdec;
    cudaGetSymbolAddress((void**)&pX,    g_X);
    cudaGetSymbolAddress((void**)&pY,    g_Ybuf);
    cudaGetSymbolAddress((void**)&pgi,   g_gi);
    cudaGetSymbolAddress((void**)&pWTih, g_WTih);
    cudaGetSymbolAddress((void**)&pWThh, g_WThh);
    cudaGetSymbolAddress((void**)&pfcT,  g_fcT);
    cudaGetSymbolAddress((void**)&phenc, g_hid_enc);
    cudaGetSymbolAddress((void**)&phdec, g_hid_dec);

    dim3 tb(32, 8);
    dim3 tW(EMB / 32, G3 / 32);          // transpose grids for Wih/Whh (1536x512)

    // ----- encoder -----
    embed_kernel<<<BATCH * SRC_T, 128>>>(src, SRC_T, enc_emb, pX, SRC_T);
    for (int l = 0; l < NLAYERS; l++) {
        transpose_kernel<<<tW, tb>>>(enc_Wih + (size_t)l * G3 * EMB, pWTih, G3, EMB);
        transpose_kernel<<<tW, tb>>>(enc_Whh + (size_t)l * G3 * HID, pWThh, G3, HID);
        const float* Ain = (l == 0) ? pX : pY;
        float*       Yout = (l == 0) ? pY : pX;
        sgemm_bias<<<dim3(G3 / 128, (BATCH * SRC_T + 127) / 128), 256>>>(
            Ain, pWTih, pgi, enc_bih + l * G3, BATCH * SRC_T, G3, EMB, 0);
        gru_layer_kernel<<<RBLK, 256>>>(pgi, pWThh, enc_bhh + l * G3, nullptr,
                                        Yout, phenc + l * BATCH * HID, SRC_T);
    }

    // ----- decoder -----
    embed_kernel<<<BATCH * DEC_T, 128>>>(trg, SRC_T, dec_emb, pX, DEC_T);
    const int MD = BATCH * DEC_T;   // 8128
    for (int l = 0; l < NLAYERS; l++) {
        transpose_kernel<<<tW, tb>>>(dec_Wih + (size_t)l * G3 * EMB, pWTih, G3, EMB);
        transpose_kernel<<<tW, tb>>>(dec_Whh + (size_t)l * G3 * HID, pWThh, G3, HID);
        const float* Ain = (l == 0) ? pX : pY;
        float*       Yout = (l == 0) ? pY : pX;
        sgemm_bias<<<dim3(G3 / 128, (MD + 127) / 128), 256>>>(
            Ain, pWTih, pgi, dec_bih + l * G3, MD, G3, EMB, 0);
        gru_layer_kernel<<<RBLK, 256>>>(pgi, pWThh, dec_bhh + l * G3,
                                        phenc + l * BATCH * HID,
                                        Yout, phdec + l * BATCH * HID, DEC_T);
    }

    // ----- output head -----
    zero_t0_kernel<<<(BATCH * VOCAB + 255) / 256, 256>>>(out);
    transpose_kernel<<<dim3(HID / 32, (VOCAB + 31) / 32), tb>>>(fc_W, pfcT, VOCAB, HID);
    sgemm_bias<<<dim3((VOCAB + 127) / 128, (MD + 127) / 128), 256>>>(
        pX, pfcT, out, fc_b, MD, VOCAB, HID, 1);
}

// round 7
// speedup vs baseline: 1.2068x; 1.0152x over previous
#include <cuda_runtime.h>
#include <cstddef>

#define BATCH   64
#define SRC_T   128
#define DEC_T   127
#define EMB     512
#define HID     512
#define G3      1536
#define VOCAB   10000
#define NLAYERS 2
#define RBLK    128   // persistent recurrence blocks (<= 148 SMs, guaranteed co-resident)

// ---------------- scratch (device globals; no runtime allocation) ----------------
__device__ float g_X   [BATCH*SRC_T*EMB];     // ping
__device__ float g_Ybuf[BATCH*SRC_T*EMB];     // pong
__device__ float g_gi  [BATCH*SRC_T*G3];      // precomputed input gates
__device__ float g_WTih[EMB*G3];              // transposed Wih of current layer
__device__ float g_WThh[HID*G3];              // transposed Whh of current layer
__device__ float g_fcT [HID*VOCAB];           // transposed fc_W
__device__ float g_h   [BATCH*HID];           // recurrent state (cg access only)
__device__ float g_hid_enc[NLAYERS*BATCH*HID];
__device__ float g_hid_dec[NLAYERS*BATCH*HID];
__device__ float g_ghp [8][BATCH*G3];         // K-split partial sums (cg access only)
__device__ unsigned g_bar_count;
__device__ unsigned g_bar_gen;

// ---------------- memory-model primitives ----------------
__device__ __forceinline__ unsigned ld_relaxed_u32(const unsigned* p) {
    unsigned v;
    asm volatile("ld.relaxed.gpu.global.u32 %0, [%1];" : "=r"(v) : "l"(p) : "memory");
    return v;
}
__device__ __forceinline__ unsigned ld_acquire_u32(const unsigned* p) {
    unsigned v;
    asm volatile("ld.acquire.gpu.global.u32 %0, [%1];" : "=r"(v) : "l"(p) : "memory");
    return v;
}
__device__ __forceinline__ void st_relaxed_u32(unsigned* p, unsigned v) {
    asm volatile("st.relaxed.gpu.global.u32 [%0], %1;" :: "l"(p), "r"(v) : "memory");
}
__device__ __forceinline__ void st_release_u32(unsigned* p, unsigned v) {
    asm volatile("st.release.gpu.global.u32 [%0], %1;" :: "l"(p), "r"(v) : "memory");
}
// Return-free arrival: REDG pipelines at ~0.854 cyc/op on one address (no RMW
// return serialization like ATOM's 32 cyc/op).
__device__ __forceinline__ void red_add_release(unsigned* p, unsigned v) {
    asm volatile("red.release.gpu.global.add.u32 [%0], %1;" :: "l"(p), "r"(v) : "memory");
}
// L1-bypassing (L2-coherent) data accessors for cross-block traffic.
__device__ __forceinline__ float ld_cg(const float* p) {
    float v; asm volatile("ld.global.cg.f32 %0, [%1];" : "=f"(v) : "l"(p)); return v;
}
__device__ __forceinline__ void st_cg(float* p, float v) {
    asm volatile("st.global.cg.f32 [%0], %1;" :: "l"(p), "f"(v));
}

// ---------------- grid barrier: red-arrive + single-observer release ----------
// Arrive: red.release (fire-and-forget, pipelined in LTS).
// Block 0 polls count (relaxed), acquires, resets, releases generation.
// Others poll generation (relaxed), then acquire once on detection.
__device__ __forceinline__ void gbar() {
    __syncthreads();
    if (threadIdx.x == 0) {
        unsigned gen = ld_relaxed_u32(&g_bar_gen);   // stable until release (needs our arrival)
        red_add_release(&g_bar_count, 1u);
        if (blockIdx.x == 0) {
            while (ld_relaxed_u32(&g_bar_count) != RBLK) { }
            (void)ld_acquire_u32(&g_bar_count);      // sync with all arrivers
            st_relaxed_u32(&g_bar_count, 0u);        // ordered before release below
            st_release_u32(&g_bar_gen, gen + 1u);
        } else {
            while (ld_relaxed_u32(&g_bar_gen) == gen) { }
            (void)ld_acquire_u32(&g_bar_gen);        // sync with releaser
        }
    }
    __syncthreads();
}

// ---------------- embedding gather ----------------
__global__ void embed_kernel(const int* __restrict__ tok, int tokStride,
                             const float* __restrict__ emb,
                             float* __restrict__ X, int T) {
    int m = blockIdx.x;
    int b = m / T, t = m - b * T;
    int v = tok[b * tokStride + t];
    const float4* s = (const float4*)(emb + (size_t)v * EMB);
    float4* d = (float4*)(X + (size_t)m * EMB);
    d[threadIdx.x] = s[threadIdx.x];
}

// ---------------- transpose: D[C][R] = S[R][C] ----------------
__global__ void transpose_kernel(const float* __restrict__ S, float* __restrict__ D,
                                 int R, int C) {
    __shared__ float tile[32][33];
    int c0 = blockIdx.x * 32, r0 = blockIdx.y * 32;
    int x = threadIdx.x, y = threadIdx.y;
    #pragma unroll
    for (int i = 0; i < 32; i += 8) {
        int r = r0 + y + i, c = c0 + x;
        if (r < R && c < C) tile[y + i][x] = S[(size_t)r * C + c];
    }
    __syncthreads();
    #pragma unroll
    for (int i = 0; i < 32; i += 8) {
        int c = c0 + y + i, r = r0 + x;
        if (r < R && c < C) D[(size_t)c * R + r] = tile[x][y + i];
    }
}

// ---------------- fp32 SGEMM, double-buffered: C = A@Bm + bias ----------------
// cmode 0: C row = m.  cmode 1 (FC head): m = b*127+t -> C row = b*128 + t + 1.
__global__ void __launch_bounds__(256) sgemm_bias(
    const float* __restrict__ A, const float* __restrict__ Bm,
    float* __restrict__ C, const float* __restrict__ bias,
    int M, int N, int K, int cmode) {
    const int BM = 128, BN = 128, BK = 8;
    __shared__ float As[2][BK][BM];
    __shared__ float Bs[2][BK][BN];
    int tid = threadIdx.x;
    int tx = tid & 15, ty = tid >> 4;
    int m_base = blockIdx.y * BM, n_base = blockIdx.x * BN;
    int arow = tid >> 1, acol = (tid & 1) * 4;
    int brow = tid >> 5, bcol = (tid & 31) * 4;
    const int am = m_base + arow;
    const int bn = n_base + bcol;
    const int nIt = K / BK;
    float acc[8][8] = {};

    // prologue: tile 0 -> buffer 0
    {
        float4 av = make_float4(0.f, 0.f, 0.f, 0.f);
        if (am < M) av = *(const float4*)(A + (size_t)am * K + acol);
        As[0][acol + 0][arow] = av.x; As[0][acol + 1][arow] = av.y;
        As[0][acol + 2][arow] = av.z; As[0][acol + 3][arow] = av.w;
        float4 bv = make_float4(0.f, 0.f, 0.f, 0.f);
        if (bn < N) bv = *(const float4*)(Bm + (size_t)brow * N + bn);
        *(float4*)&Bs[0][brow][bcol] = bv;
    }
    __syncthreads();

    for (int it = 0; it < nIt; it++) {
        int cur = it & 1;
        float4 av, bv;
        bool more = (it + 1 < nIt);
        if (more) {                       // issue next-tile loads before compute
            int k0 = (it + 1) * BK;
            av = make_float4(0.f, 0.f, 0.f, 0.f);
            if (am < M) av = *(const float4*)(A + (size_t)am * K + k0 + acol);
            bv = make_float4(0.f, 0.f, 0.f, 0.f);
            if (bn < N) bv = *(const float4*)(Bm + (size_t)(k0 + brow) * N + bn);
        }
        #pragma unroll
        for (int k = 0; k < BK; k++) {
            float a[8], b[8];
            #pragma unroll
            for (int i = 0; i < 4; i++) {
                a[i]     = As[cur][k][ty * 4 + i];
                a[4 + i] = As[cur][k][64 + ty * 4 + i];
                b[i]     = Bs[cur][k][tx * 4 + i];
                b[4 + i] = Bs[cur][k][64 + tx * 4 + i];
            }
            #pragma unroll
            for (int i = 0; i < 8; i++)
                #pragma unroll
                for (int j = 0; j < 8; j++) acc[i][j] += a[i] * b[j];
        }
        if (more) {
            int nxt = cur ^ 1;
            As[nxt][acol + 0][arow] = av.x; As[nxt][acol + 1][arow] = av.y;
            As[nxt][acol + 2][arow] = av.z; As[nxt][acol + 3][arow] = av.w;
            *(float4*)&Bs[nxt][brow][bcol] = bv;
        }
        __syncthreads();
    }

    #pragma unroll
    for (int i = 0; i < 8; i++) {
        int ml = (i < 4) ? (ty * 4 + i) : (64 + ty * 4 + i - 4);
        int m = m_base + ml;
        if (m >= M) continue;
        size_t crow;
        if (cmode == 0) crow = (size_t)m;
        else { int bb = m / DEC_T, tt = m - bb * DEC_T; crow = (size_t)bb * SRC_T + tt + 1; }
        float* crp = C + crow * (size_t)N;
        #pragma unroll
        for (int jg = 0; jg < 2; jg++) {
            int n = n_base + jg * 64 + tx * 4;
            if (n < N) {
                float4 v;
                v.x = acc[i][jg * 4 + 0] + bias[n + 0];
                v.y = acc[i][jg * 4 + 1] + bias[n + 1];
                v.z = acc[i][jg * 4 + 2] + bias[n + 2];
                v.w = acc[i][jg * 4 + 3] + bias[n + 3];
                *(float4*)(crp + n) = v;
            }
        }
    }
}

// ---------------- persistent GRU layer recurrence ----------------
__global__ void __launch_bounds__(256) gru_layer_kernel(
    const float* __restrict__ gi, const float* __restrict__ WhhT,
    const float* __restrict__ bhh, const float* __restrict__ hinit,
    float* __restrict__ Y, float* __restrict__ hfinal, int T) {
    __shared__ float sh_hT[64][65];   // [k][m]  (65-stride: conflict-free stores; scalar reads)
    __shared__ float sh_w[64][96];    // [k][n]  loop-invariant weight tile
    int blk = blockIdx.x, tid = threadIdx.x;

    // this thread owns exactly one state element e (RBLK*256 == BATCH*HID)
    const int e = blk * 256 + tid;
    const int b = e >> 9, j = e & 511;
    float hreg = hinit ? hinit[e] : 0.0f;
    st_cg(&g_h[e], hreg);

    // loop-invariant gate biases in registers
    const float bh_r = bhh[j];
    const float bh_z = bhh[512 + j];
    const float bh_n = bhh[1024 + j];

    const int kc = blk >> 4, nt = blk & 15;
    const int k0 = kc * 64, n0 = nt * 96;
    const int tx = tid & 15, ty = tid >> 4;   // tx: 6-wide n, ty: 4-wide m

    // load weight tile once (invariant across all T steps)
    #pragma unroll
    for (int r = 0; r < 24; ++r) {
        int idx = r * 256 + tid;
        int k = idx / 96, n = idx - k * 96;
        sh_w[k][n] = WhhT[(size_t)(k0 + k) * G3 + n0 + n];
    }
    gbar();

    for (int t = 0; t < T; ++t) {
        // prefetch this step's input-gate values (kernel-constant data; plain loads)
        const float* gir = gi + ((size_t)b * T + t) * G3;
        float gi_r = __ldg(gir + j);
        float gi_z = __ldg(gir + 512 + j);
        float gi_n = __ldg(gir + 1024 + j);

        // ---- phase A: partial gh = h[:, k0:k0+64] @ WhhT[k0:k0+64, n0:n0+96]
        #pragma unroll
        for (int r = 0; r < 16; ++r) {
            int idx = r * 256 + tid;
            int m = idx >> 6, k = idx & 63;
            sh_hT[k][m] = ld_cg(&g_h[m * HID + k0 + k]);
        }
        __syncthreads();
        float acc[4][6] = {};
        #pragma unroll
        for (int k = 0; k < 64; ++k) {
            float am[4], bb[6];
            #pragma unroll
            for (int i = 0; i < 4; i++) am[i] = sh_hT[k][ty * 4 + i];
            #pragma unroll
            for (int jn = 0; jn < 6; jn++) bb[jn] = sh_w[k][tx * 6 + jn];
            #pragma unroll
            for (int i = 0; i < 4; i++)
                #pragma unroll
                for (int jn = 0; jn < 6; jn++) acc[i][jn] += am[i] * bb[jn];
        }
        #pragma unroll
        for (int i = 0; i < 4; i++) {
            int m = ty * 4 + i;
            float* dst = &g_ghp[kc][m * G3 + n0 + tx * 6];
            #pragma unroll
            for (int jn = 0; jn < 6; jn++) st_cg(dst + jn, acc[i][jn]);
        }
        gbar();
        // ---- phase B: gates + state update (one thread per (b, j))
        {
            float s0 = 0.f, s1 = 0.f, s2 = 0.f;
            #pragma unroll
            for (int c = 0; c < 8; c++) {
                const float* p = &g_ghp[c][b * G3];
                s0 += ld_cg(p + j);
                s1 += ld_cg(p + 512 + j);
                s2 += ld_cg(p + 1024 + j);
            }
            float r = 1.f / (1.f + __expf(-(gi_r + s0 + bh_r)));
            float z = 1.f / (1.f + __expf(-(gi_z + s1 + bh_z)));
            float nn = tanhf(gi_n + r * (s2 + bh_n));
            float hn = (1.f - z) * nn + z * hreg;
            Y[((size_t)b * T + t) * HID + j] = hn;   // consumed by later kernels only
            st_cg(&g_h[e], hn);
            hreg = hn;
        }
        gbar();
    }
    hfinal[e] = hreg;
}

// ---------------- zero t=0 output plane ----------------
__global__ void zero_t0_kernel(float* __restrict__ out) {
    int idx = blockIdx.x * 256 + threadIdx.x;
    if (idx < BATCH * VOCAB) {
        int b = idx / VOCAB, v = idx - b * VOCAB;
        out[(size_t)b * SRC_T * VOCAB + v] = 0.0f;
    }
}

// ---------------- host driver ----------------
extern "C" void kernel_launch(void* const* d_in, const int* in_sizes, int n_in,
                              void* d_out, int out_size) {
    const int*   src     = (const int*)  d_in[0];
    const int*   trg     = (const int*)  d_in[1];
    const float* enc_emb = (const float*)d_in[2];
    const float* enc_Wih = (const float*)d_in[3];
    const float* enc_Whh = (const float*)d_in[4];
    const float* enc_bih = (const float*)d_in[5];
    const float* enc_bhh = (const float*)d_in[6];
    const float* dec_emb = (const float*)d_in[7];
    const float* dec_Wih = (const float*)d_in[8];
    const float* dec_Whh = (const float*)d_in[9];
    const float* dec_bih = (const float*)d_in[10];
    const float* dec_bhh = (const float*)d_in[11];
    const float* fc_W    = (const float*)d_in[12];
    const float* fc_b    = (const float*)d_in[13];
    float* out = (float*)d_out;

    float *pX, *pY, *pgi, *pWTih, *pWThh, *pfcT, *phenc, *phdec;
    cudaGetSymbolAddress((void**)&pX,    g_X);
    cudaGetSymbolAddress((void**)&pY,    g_Ybuf);
    cudaGetSymbolAddress((void**)&pgi,   g_gi);
    cudaGetSymbolAddress((void**)&pWTih, g_WTih);
    cudaGetSymbolAddress((void**)&pWThh, g_WThh);
    cudaGetSymbolAddress((void**)&pfcT,  g_fcT);
    cudaGetSymbolAddress((void**)&phenc, g_hid_enc);
    cudaGetSymbolAddress((void**)&phdec, g_hid_dec);

    dim3 tb(32, 8);
    dim3 tW(EMB / 32, G3 / 32);          // transpose grids for Wih/Whh (1536x512)

    // ----- encoder -----
    embed_kernel<<<BATCH * SRC_T, 128>>>(src, SRC_T, enc_emb, pX, SRC_T);
    for (int l = 0; l < NLAYERS; l++) {
        transpose_kernel<<<tW, tb>>>(enc_Wih + (size_t)l * G3 * EMB, pWTih, G3, EMB);
        transpose_kernel<<<tW, tb>>>(enc_Whh + (size_t)l * G3 * HID, pWThh, G3, HID);
        const float* Ain = (l == 0) ? pX : pY;
        float*       Yout = (l == 0) ? pY : pX;
        sgemm_bias<<<dim3(G3 / 128, (BATCH * SRC_T + 127) / 128), 256>>>(
            Ain, pWTih, pgi, enc_bih + l * G3, BATCH * SRC_T, G3, EMB, 0);
        gru_layer_kernel<<<RBLK, 256>>>(pgi, pWThh, enc_bhh + l * G3, nullptr,
                                        Yout, phenc + l * BATCH * HID, SRC_T);
    }

    // ----- decoder -----
    embed_kernel<<<BATCH * DEC_T, 128>>>(trg, SRC_T, dec_emb, pX, DEC_T);
    const int MD = BATCH * DEC_T;   // 8128
    for (int l = 0; l < NLAYERS; l++) {
        transpose_kernel<<<tW, tb>>>(dec_Wih + (size_t)l * G3 * EMB, pWTih, G3, EMB);
        transpose_kernel<<<tW, tb>>>(dec_Whh + (size_t)l * G3 * HID, pWThh, G3, HID);
        const float* Ain = (l == 0) ? pX : pY;
        float*       Yout = (l == 0) ? pY : pX;
        sgemm_bias<<<dim3(G3 / 128, (MD + 127) / 128), 256>>>(
            Ain, pWTih, pgi, dec_bih + l * G3, MD, G3, EMB, 0);
        gru_layer_kernel<<<RBLK, 256>>>(pgi, pWThh, dec_bhh + l * G3,
                                        phenc + l * BATCH * HID,
                                        Yout, phdec + l * BATCH * HID, DEC_T);
    }

    // ----- output head -----
    zero_t0_kernel<<<(BATCH * VOCAB + 255) / 256, 256>>>(out);
    transpose_kernel<<<dim3(HID / 32, (VOCAB + 31) / 32), tb>>>(fc_W, pfcT, VOCAB, HID);
    sgemm_bias<<<dim3((VOCAB + 127) / 128, (MD + 127) / 128), 256>>>(
        pX, pfcT, out, fc_b, MD, VOCAB, HID, 1);
}

// round 8
// speedup vs baseline: 1.2825x; 1.0627x over previous
#include <cuda_runtime.h>
#include <cstddef>

#define BATCH   64
#define SRC_T   128
#define DEC_T   127
#define EMB     512
#define HID     512
#define G3      1536
#define VOCAB   10000
#define NLAYERS 2
#define RBLK    128   // persistent recurrence blocks (<= 148 SMs, guaranteed co-resident)

// ---------------- scratch (device globals; no runtime allocation) ----------------
__device__ float g_X   [BATCH*SRC_T*EMB];     // ping
__device__ float g_Ybuf[BATCH*SRC_T*EMB];     // pong
__device__ float g_gi  [BATCH*SRC_T*G3];      // precomputed input gates
__device__ float g_WTih[EMB*G3];              // transposed Wih of current layer
__device__ float g_WThh[HID*G3];              // transposed Whh of current layer
__device__ float g_fcT [HID*VOCAB];           // transposed fc_W
__device__ float g_h   [BATCH*HID];           // recurrent state (cg access only)
__device__ float g_hid_enc[NLAYERS*BATCH*HID];
__device__ float g_hid_dec[NLAYERS*BATCH*HID];
__device__ float g_ghp [8][BATCH*G3];         // K-split partial sums (cg access only)
__device__ unsigned g_bar_count;
__device__ unsigned g_bar_gen;

// ---------------- memory-model primitives ----------------
__device__ __forceinline__ unsigned ld_relaxed_u32(const unsigned* p) {
    unsigned v;
    asm volatile("ld.relaxed.gpu.global.u32 %0, [%1];" : "=r"(v) : "l"(p) : "memory");
    return v;
}
__device__ __forceinline__ unsigned ld_acquire_u32(const unsigned* p) {
    unsigned v;
    asm volatile("ld.acquire.gpu.global.u32 %0, [%1];" : "=r"(v) : "l"(p) : "memory");
    return v;
}
__device__ __forceinline__ void st_relaxed_u32(unsigned* p, unsigned v) {
    asm volatile("st.relaxed.gpu.global.u32 [%0], %1;" :: "l"(p), "r"(v) : "memory");
}
__device__ __forceinline__ void st_release_u32(unsigned* p, unsigned v) {
    asm volatile("st.release.gpu.global.u32 [%0], %1;" :: "l"(p), "r"(v) : "memory");
}
// Return-free arrival: REDG pipelines (no RMW-return serialization).
__device__ __forceinline__ void red_add_release(unsigned* p, unsigned v) {
    asm volatile("red.release.gpu.global.add.u32 [%0], %1;" :: "l"(p), "r"(v) : "memory");
}
// L1-bypassing (L2-coherent) data accessors for cross-block traffic.
__device__ __forceinline__ float ld_cg(const float* p) {
    float v; asm volatile("ld.global.cg.f32 %0, [%1];" : "=f"(v) : "l"(p)); return v;
}
__device__ __forceinline__ void st_cg(float* p, float v) {
    asm volatile("st.global.cg.f32 [%0], %1;" :: "l"(p), "f"(v));
}
__device__ __forceinline__ float2 ld_shared_f2(const float* p) {
    float2 v;
    asm volatile("ld.shared.v2.f32 {%0,%1}, [%2];" : "=f"(v.x), "=f"(v.y)
                 : "l"(__cvta_generic_to_shared(p)));
    return v;
}

// ---------------- grid barrier: red-arrive + single-observer release ----------
__device__ __forceinline__ void gbar() {
    __syncthreads();
    if (threadIdx.x == 0) {
        unsigned gen = ld_relaxed_u32(&g_bar_gen);   // stable until release (needs our arrival)
        red_add_release(&g_bar_count, 1u);
        if (blockIdx.x == 0) {
            while (ld_relaxed_u32(&g_bar_count) != RBLK) { }
            (void)ld_acquire_u32(&g_bar_count);      // sync with all arrivers
            st_relaxed_u32(&g_bar_count, 0u);        // ordered before release below
            st_release_u32(&g_bar_gen, gen + 1u);
        } else {
            while (ld_relaxed_u32(&g_bar_gen) == gen) { }
            (void)ld_acquire_u32(&g_bar_gen);        // sync with releaser
        }
    }
    __syncthreads();
}

// ---------------- embedding gather ----------------
__global__ void embed_kernel(const int* __restrict__ tok, int tokStride,
                             const float* __restrict__ emb,
                             float* __restrict__ X, int T) {
    int m = blockIdx.x;
    int b = m / T, t = m - b * T;
    int v = tok[b * tokStride + t];
    const float4* s = (const float4*)(emb + (size_t)v * EMB);
    float4* d = (float4*)(X + (size_t)m * EMB);
    d[threadIdx.x] = s[threadIdx.x];
}

// ---------------- transpose: D[C][R] = S[R][C] ----------------
__global__ void transpose_kernel(const float* __restrict__ S, float* __restrict__ D,
                                 int R, int C) {
    __shared__ float tile[32][33];
    int c0 = blockIdx.x * 32, r0 = blockIdx.y * 32;
    int x = threadIdx.x, y = threadIdx.y;
    #pragma unroll
    for (int i = 0; i < 32; i += 8) {
        int r = r0 + y + i, c = c0 + x;
        if (r < R && c < C) tile[y + i][x] = S[(size_t)r * C + c];
    }
    __syncthreads();
    #pragma unroll
    for (int i = 0; i < 32; i += 8) {
        int c = c0 + y + i, r = r0 + x;
        if (r < R && c < C) D[(size_t)c * R + r] = tile[x][y + i];
    }
}

// ---------------- fp32 SGEMM, single-buffer BK=16: C = A@Bm + bias ------------
// cmode 0: C row = m.  cmode 1 (FC head): m = b*127+t -> C row = b*128 + t + 1.
__global__ void __launch_bounds__(256, 2) sgemm_bias(
    const float* __restrict__ A, const float* __restrict__ Bm,
    float* __restrict__ C, const float* __restrict__ bias,
    int M, int N, int K, int cmode) {
    const int BM = 128, BN = 128, BK = 16;
    __shared__ float As[BK][BM];
    __shared__ float Bs[BK][BN];
    int tid = threadIdx.x;
    int tx = tid & 15, ty = tid >> 4;
    int m_base = blockIdx.y * BM, n_base = blockIdx.x * BN;
    int arow = tid >> 1, acol = (tid & 1) * 8;   // two float4 along K per thread
    int brow = tid >> 5, bcol = (tid & 31) * 4;  // rows brow, brow+8
    const int am = m_base + arow;
    const int bn = n_base + bcol;
    float acc[8][8] = {};
    for (int k0 = 0; k0 < K; k0 += BK) {
        #pragma unroll
        for (int h = 0; h < 2; h++) {
            int ac = acol + h * 4;
            float4 av = make_float4(0.f, 0.f, 0.f, 0.f);
            if (am < M) av = *(const float4*)(A + (size_t)am * K + k0 + ac);
            As[ac + 0][arow] = av.x; As[ac + 1][arow] = av.y;
            As[ac + 2][arow] = av.z; As[ac + 3][arow] = av.w;
        }
        #pragma unroll
        for (int h = 0; h < 2; h++) {
            int br = brow + h * 8;
            float4 bv = make_float4(0.f, 0.f, 0.f, 0.f);
            if (bn < N) bv = *(const float4*)(Bm + (size_t)(k0 + br) * N + bn);
            *(float4*)&Bs[br][bcol] = bv;
        }
        __syncthreads();
        #pragma unroll
        for (int k = 0; k < BK; k++) {
            float a[8], b[8];
            #pragma unroll
            for (int i = 0; i < 4; i++) {
                a[i]     = As[k][ty * 4 + i];
                a[4 + i] = As[k][64 + ty * 4 + i];
                b[i]     = Bs[k][tx * 4 + i];
                b[4 + i] = Bs[k][64 + tx * 4 + i];
            }
            #pragma unroll
            for (int i = 0; i < 8; i++)
                #pragma unroll
                for (int j = 0; j < 8; j++) acc[i][j] += a[i] * b[j];
        }
        __syncthreads();
    }
    #pragma unroll
    for (int i = 0; i < 8; i++) {
        int ml = (i < 4) ? (ty * 4 + i) : (64 + ty * 4 + i - 4);
        int m = m_base + ml;
        if (m >= M) continue;
        size_t crow;
        if (cmode == 0) crow = (size_t)m;
        else { int bb = m / DEC_T, tt = m - bb * DEC_T; crow = (size_t)bb * SRC_T + tt + 1; }
        float* crp = C + crow * (size_t)N;
        #pragma unroll
        for (int jg = 0; jg < 2; jg++) {
            int n = n_base + jg * 64 + tx * 4;
            if (n < N) {
                float4 v;
                v.x = acc[i][jg * 4 + 0] + bias[n + 0];
                v.y = acc[i][jg * 4 + 1] + bias[n + 1];
                v.z = acc[i][jg * 4 + 2] + bias[n + 2];
                v.w = acc[i][jg * 4 + 3] + bias[n + 3];
                *(float4*)(crp + n) = v;
            }
        }
    }
}

// ---------------- persistent GRU layer recurrence ----------------
__global__ void __launch_bounds__(256) gru_layer_kernel(
    const float* __restrict__ gi, const float* __restrict__ WhhT,
    const float* __restrict__ bhh, const float* __restrict__ hinit,
    float* __restrict__ Y, float* __restrict__ hfinal, int T) {
    __shared__ float sh_hT[64][65];   // [k][m]  (65-stride: conflict-free stores; scalar reads)
    __shared__ float sh_w[64][96];    // [k][n]  loop-invariant weight tile
    int blk = blockIdx.x, tid = threadIdx.x;

    // this thread owns exactly one state element e (RBLK*256 == BATCH*HID)
    const int e = blk * 256 + tid;
    const int b = e >> 9, j = e & 511;
    float hreg = hinit ? hinit[e] : 0.0f;
    st_cg(&g_h[e], hreg);

    // loop-invariant gate biases in registers
    const float bh_r = bhh[j];
    const float bh_z = bhh[512 + j];
    const float bh_n = bhh[1024 + j];

    const int kc = blk >> 4, nt = blk & 15;
    const int k0 = kc * 64, n0 = nt * 96;
    const int tx = tid & 15, ty = tid >> 4;   // tx: 6-wide n, ty: 4-wide m

    // load weight tile once (invariant across all T steps)
    #pragma unroll
    for (int r = 0; r < 24; ++r) {
        int idx = r * 256 + tid;
        int k = idx / 96, n = idx - k * 96;
        sh_w[k][n] = WhhT[(size_t)(k0 + k) * G3 + n0 + n];
    }
    gbar();

    for (int t = 0; t < T; ++t) {
        // prefetch this step's input-gate values (kernel-constant data; plain loads)
        const float* gir = gi + ((size_t)b * T + t) * G3;
        float gi_r = __ldg(gir + j);
        float gi_z = __ldg(gir + 512 + j);
        float gi_n = __ldg(gir + 1024 + j);

        // ---- phase A: partial gh = h[:, k0:k0+64] @ WhhT[k0:k0+64, n0:n0+96]
        #pragma unroll
        for (int r = 0; r < 16; ++r) {
            int idx = r * 256 + tid;
            int m = idx >> 6, k = idx & 63;
            sh_hT[k][m] = ld_cg(&g_h[m * HID + k0 + k]);
        }
        __syncthreads();
        float acc[4][6] = {};
        #pragma unroll
        for (int k = 0; k < 64; ++k) {
            float am[4];
            #pragma unroll
            for (int i = 0; i < 4; i++) am[i] = sh_hT[k][ty * 4 + i];
            // 6 weight floats as 3x LDS.64 (tx*6 floats -> 8B aligned)
            float2 b01 = ld_shared_f2(&sh_w[k][tx * 6 + 0]);
            float2 b23 = ld_shared_f2(&sh_w[k][tx * 6 + 2]);
            float2 b45 = ld_shared_f2(&sh_w[k][tx * 6 + 4]);
            float bb[6] = {b01.x, b01.y, b23.x, b23.y, b45.x, b45.y};
            #pragma unroll
            for (int i = 0; i < 4; i++)
                #pragma unroll
                for (int jn = 0; jn < 6; jn++) acc[i][jn] += am[i] * bb[jn];
        }
        #pragma unroll
        for (int i = 0; i < 4; i++) {
            int m = ty * 4 + i;
            float* dst = &g_ghp[kc][m * G3 + n0 + tx * 6];
            #pragma unroll
            for (int jn = 0; jn < 6; jn++) st_cg(dst + jn, acc[i][jn]);
        }
        gbar();
        // ---- phase B: gates + state update (one thread per (b, j))
        {
            float s0 = 0.f, s1 = 0.f, s2 = 0.f;
            #pragma unroll
            for (int c = 0; c < 8; c++) {
                const float* p = &g_ghp[c][b * G3];
                s0 += ld_cg(p + j);
                s1 += ld_cg(p + 512 + j);
                s2 += ld_cg(p + 1024 + j);
            }
            float r = 1.f / (1.f + __expf(-(gi_r + s0 + bh_r)));
            float z = 1.f / (1.f + __expf(-(gi_z + s1 + bh_z)));
            float nn = tanhf(gi_n + r * (s2 + bh_n));
            float hn = (1.f - z) * nn + z * hreg;
            Y[((size_t)b * T + t) * HID + j] = hn;   // consumed by later kernels only
            st_cg(&g_h[e], hn);
            hreg = hn;
        }
        gbar();
    }
    hfinal[e] = hreg;
}

// ---------------- zero t=0 output plane ----------------
__global__ void zero_t0_kernel(float* __restrict__ out) {
    int idx = blockIdx.x * 256 + threadIdx.x;
    if (idx < BATCH * VOCAB) {
        int b = idx / VOCAB, v = idx - b * VOCAB;
        out[(size_t)b * SRC_T * VOCAB + v] = 0.0f;
    }
}

// ---------------- host driver ----------------
extern "C" void kernel_launch(void* const* d_in, const int* in_sizes, int n_in,
                              void* d_out, int out_size) {
    const int*   src     = (const int*)  d_in[0];
    const int*   trg     = (const int*)  d_in[1];
    const float* enc_emb = (const float*)d_in[2];
    const float* enc_Wih = (const float*)d_in[3];
    const float* enc_Whh = (const float*)d_in[4];
    const float* enc_bih = (const float*)d_in[5];
    const float* enc_bhh = (const float*)d_in[6];
    const float* dec_emb = (const float*)d_in[7];
    const float* dec_Wih = (const float*)d_in[8];
    const float* dec_Whh = (const float*)d_in[9];
    const float* dec_bih = (const float*)d_in[10];
    const float* dec_bhh = (const float*)d_in[11];
    const float* fc_W    = (const float*)d_in[12];
    const float* fc_b    = (const float*)d_in[13];
    float* out = (float*)d_out;

    float *pX, *pY, *pgi, *pWTih, *pWThh, *pfcT, *phenc, *phdec;
    cudaGetSymbolAddress((void**)&pX,    g_X);
    cudaGetSymbolAddress((void**)&pY,    g_Ybuf);
    cudaGetSymbolAddress((void**)&pgi,   g_gi);
    cudaGetSymbolAddress((void**)&pWTih, g_WTih);
    cudaGetSymbolAddress((void**)&pWThh, g_WThh);
    cudaGetSymbolAddress((void**)&pfcT,  g_fcT);
    cudaGetSymbolAddress((void**)&phenc, g_hid_enc);
    cudaGetSymbolAddress((void**)&phdec, g_hid_dec);

    dim3 tb(32, 8);
    dim3 tW(EMB / 32, G3 / 32);          // transpose grids for Wih/Whh (1536x512)

    // ----- encoder -----
    embed_kernel<<<BATCH * SRC_T, 128>>>(src, SRC_T, enc_emb, pX, SRC_T);
    for (int l = 0; l < NLAYERS; l++) {
        transpose_kernel<<<tW, tb>>>(enc_Wih + (size_t)l * G3 * EMB, pWTih, G3, EMB);
        transpose_kernel<<<tW, tb>>>(enc_Whh + (size_t)l * G3 * HID, pWThh, G3, HID);
        const float* Ain = (l == 0) ? pX : pY;
        float*       Yout = (l == 0) ? pY : pX;
        sgemm_bias<<<dim3(G3 / 128, (BATCH * SRC_T + 127) / 128), 256>>>(
            Ain, pWTih, pgi, enc_bih + l * G3, BATCH * SRC_T, G3, EMB, 0);
        gru_layer_kernel<<<RBLK, 256>>>(pgi, pWThh, enc_bhh + l * G3, nullptr,
                                        Yout, phenc + l * BATCH * HID, SRC_T);
    }

    // ----- decoder -----
    embed_kernel<<<BATCH * DEC_T, 128>>>(trg, SRC_T, dec_emb, pX, DEC_T);
    const int MD = BATCH * DEC_T;   // 8128
    for (int l = 0; l < NLAYERS; l++) {
        transpose_kernel<<<tW, tb>>>(dec_Wih + (size_t)l * G3 * EMB, pWTih, G3, EMB);
        transpose_kernel<<<tW, tb>>>(dec_Whh + (size_t)l * G3 * HID, pWThh, G3, HID);
        const float* Ain = (l == 0) ? pX : pY;
        float*       Yout = (l == 0) ? pY : pX;
        sgemm_bias<<<dim3(G3 / 128, (MD + 127) / 128), 256>>>(
            Ain, pWTih, pgi, dec_bih + l * G3, MD, G3, EMB, 0);
        gru_layer_kernel<<<RBLK, 256>>>(pgi, pWThh, dec_bhh + l * G3,
                                        phenc + l * BATCH * HID,
                                        Yout, phdec + l * BATCH * HID, DEC_T);
    }

    // ----- output head -----
    zero_t0_kernel<<<(BATCH * VOCAB + 255) / 256, 256>>>(out);
    transpose_kernel<<<dim3(HID / 32, (VOCAB + 31) / 32), tb>>>(fc_W, pfcT, VOCAB, HID);
    sgemm_bias<<<dim3((VOCAB + 127) / 128, (MD + 127) / 128), 256>>>(
        pX, pfcT, out, fc_b, MD, VOCAB, HID, 1);
}

// round 10
// speedup vs baseline: 1.3649x; 1.0642x over previous
#include <cuda_runtime.h>
#include <cstddef>

#define BATCH   64
#define SRC_T   128
#define DEC_T   127
#define EMB     512
#define HID     512
#define G3      1536
#define VOCAB   10000
#define NLAYERS 2
#define RBLK    128   // persistent recurrence blocks (<= 148 SMs, guaranteed co-resident)

typedef unsigned long long u64;

// ---------------- scratch (device globals; no runtime allocation) ----------------
__device__ float g_X   [BATCH*SRC_T*EMB];     // ping
__device__ float g_Ybuf[BATCH*SRC_T*EMB];     // pong
__device__ float g_gi  [BATCH*SRC_T*G3];      // precomputed input gates
__device__ float g_WTih[EMB*G3];              // transposed Wih of current layer
__device__ float g_WThh[HID*G3];              // transposed Whh of current layer
__device__ float g_fcT [HID*VOCAB];           // transposed fc_W
__device__ float g_h   [BATCH*HID];           // recurrent state (cg access only)
__device__ float g_hid_enc[NLAYERS*BATCH*HID];
__device__ float g_hid_dec[NLAYERS*BATCH*HID];
__device__ float g_ghp [8][BATCH*G3];         // K-split partial sums (cg access only)
__device__ unsigned g_bar_count;
__device__ unsigned g_bar_gen;

// ---------------- packed f32x2 primitives (sm_103a; ptxas never emits these) ---
__device__ __forceinline__ u64 pack2(float lo, float hi) {
    u64 d; asm("mov.b64 %0, {%1,%2};" : "=l"(d) : "f"(lo), "f"(hi)); return d;
}
__device__ __forceinline__ void unpack2(float& lo, float& hi, u64 s) {
    asm("mov.b64 {%0,%1}, %2;" : "=f"(lo), "=f"(hi) : "l"(s));
}
__device__ __forceinline__ u64 ffma2(u64 a, u64 b, u64 c) {
    u64 d; asm("fma.rn.f32x2 %0, %1, %2, %3;" : "=l"(d) : "l"(a), "l"(b), "l"(c));
    return d;
}

// ---------------- memory-model primitives ----------------
__device__ __forceinline__ unsigned ld_relaxed_u32(const unsigned* p) {
    unsigned v;
    asm volatile("ld.relaxed.gpu.global.u32 %0, [%1];" : "=r"(v) : "l"(p) : "memory");
    return v;
}
__device__ __forceinline__ unsigned ld_acquire_u32(const unsigned* p) {
    unsigned v;
    asm volatile("ld.acquire.gpu.global.u32 %0, [%1];" : "=r"(v) : "l"(p) : "memory");
    return v;
}
__device__ __forceinline__ void st_relaxed_u32(unsigned* p, unsigned v) {
    asm volatile("st.relaxed.gpu.global.u32 [%0], %1;" :: "l"(p), "r"(v) : "memory");
}
__device__ __forceinline__ void st_release_u32(unsigned* p, unsigned v) {
    asm volatile("st.release.gpu.global.u32 [%0], %1;" :: "l"(p), "r"(v) : "memory");
}
__device__ __forceinline__ void red_add_release(unsigned* p, unsigned v) {
    asm volatile("red.release.gpu.global.add.u32 [%0], %1;" :: "l"(p), "r"(v) : "memory");
}
__device__ __forceinline__ float ld_cg(const float* p) {
    float v; asm volatile("ld.global.cg.f32 %0, [%1];" : "=f"(v) : "l"(p)); return v;
}
__device__ __forceinline__ void st_cg(float* p, float v) {
    asm volatile("st.global.cg.f32 [%0], %1;" :: "l"(p), "f"(v));
}
__device__ __forceinline__ float2 ld_shared_f2(const float* p) {
    float2 v;
    asm volatile("ld.shared.v2.f32 {%0,%1}, [%2];" : "=f"(v.x), "=f"(v.y)
                 : "l"(__cvta_generic_to_shared(p)));
    return v;
}

// ---------------- grid barrier: red-arrive + single-observer release ----------
__device__ __forceinline__ void gbar() {
    __syncthreads();
    if (threadIdx.x == 0) {
        unsigned gen = ld_relaxed_u32(&g_bar_gen);
        red_add_release(&g_bar_count, 1u);
        if (blockIdx.x == 0) {
            while (ld_relaxed_u32(&g_bar_count) != RBLK) { }
            (void)ld_acquire_u32(&g_bar_count);
            st_relaxed_u32(&g_bar_count, 0u);
            st_release_u32(&g_bar_gen, gen + 1u);
        } else {
            while (ld_relaxed_u32(&g_bar_gen) == gen) { }
            (void)ld_acquire_u32(&g_bar_gen);
        }
    }
    __syncthreads();
}

// ---------------- embedding gather ----------------
__global__ void embed_kernel(const int* __restrict__ tok, int tokStride,
                             const float* __restrict__ emb,
                             float* __restrict__ X, int T) {
    int m = blockIdx.x;
    int b = m / T, t = m - b * T;
    int v = tok[b * tokStride + t];
    const float4* s = (const float4*)(emb + (size_t)v * EMB);
    float4* d = (float4*)(X + (size_t)m * EMB);
    d[threadIdx.x] = s[threadIdx.x];
}

// ---------------- transpose: D[C][R] = S[R][C] ----------------
__global__ void transpose_kernel(const float* __restrict__ S, float* __restrict__ D,
                                 int R, int C) {
    __shared__ float tile[32][33];
    int c0 = blockIdx.x * 32, r0 = blockIdx.y * 32;
    int x = threadIdx.x, y = threadIdx.y;
    #pragma unroll
    for (int i = 0; i < 32; i += 8) {
        int r = r0 + y + i, c = c0 + x;
        if (r < R && c < C) tile[y + i][x] = S[(size_t)r * C + c];
    }
    __syncthreads();
    #pragma unroll
    for (int i = 0; i < 32; i += 8) {
        int c = c0 + y + i, r = r0 + x;
        if (r < R && c < C) D[(size_t)c * R + r] = tile[x][y + i];
    }
}

// ---------------- fp32 SGEMM, BK=16, f32x2 inner: C = A@Bm + bias -------------
// cmode 0: C row = m.  cmode 1 (FC head): m = b*127+t -> C row = b*128 + t + 1.
__global__ void __launch_bounds__(256, 2) sgemm_bias(
    const float* __restrict__ A, const float* __restrict__ Bm,
    float* __restrict__ C, const float* __restrict__ bias,
    int M, int N, int K, int cmode) {
    const int BM = 128, BN = 128, BK = 16;
    __shared__ float As[BK][BM];
    __shared__ float Bs[BK][BN];
    int tid = threadIdx.x;
    int tx = tid & 15, ty = tid >> 4;
    int m_base = blockIdx.y * BM, n_base = blockIdx.x * BN;
    int arow = tid >> 1, acol = (tid & 1) * 8;
    int brow = tid >> 5, bcol = (tid & 31) * 4;
    const int am = m_base + arow;
    const int bn = n_base + bcol;
    u64 acc2[8][4] = {};                 // packed pairs along n
    for (int k0 = 0; k0 < K; k0 += BK) {
        #pragma unroll
        for (int h = 0; h < 2; h++) {
            int ac = acol + h * 4;
            float4 av = make_float4(0.f, 0.f, 0.f, 0.f);
            if (am < M) av = *(const float4*)(A + (size_t)am * K + k0 + ac);
            As[ac + 0][arow] = av.x; As[ac + 1][arow] = av.y;
            As[ac + 2][arow] = av.z; As[ac + 3][arow] = av.w;
        }
        #pragma unroll
        for (int h = 0; h < 2; h++) {
            int br = brow + h * 8;
            float4 bv = make_float4(0.f, 0.f, 0.f, 0.f);
            if (bn < N) bv = *(const float4*)(Bm + (size_t)(k0 + br) * N + bn);
            *(float4*)&Bs[br][bcol] = bv;
        }
        __syncthreads();
        #pragma unroll
        for (int k = 0; k < BK; k++) {
            float a[8];
            #pragma unroll
            for (int i = 0; i < 4; i++) {
                a[i]     = As[k][ty * 4 + i];
                a[4 + i] = As[k][64 + ty * 4 + i];
            }
            float4 blo = *(const float4*)&Bs[k][tx * 4];
            float4 bhi = *(const float4*)&Bs[k][64 + tx * 4];
            u64 b2[4];
            b2[0] = pack2(blo.x, blo.y); b2[1] = pack2(blo.z, blo.w);
            b2[2] = pack2(bhi.x, bhi.y); b2[3] = pack2(bhi.z, bhi.w);
            #pragma unroll
            for (int i = 0; i < 8; i++) {
                u64 a2 = pack2(a[i], a[i]);
                #pragma unroll
                for (int j2 = 0; j2 < 4; j2++)
                    acc2[i][j2] = ffma2(a2, b2[j2], acc2[i][j2]);
            }
        }
        __syncthreads();
    }
    #pragma unroll
    for (int i = 0; i < 8; i++) {
        int ml = (i < 4) ? (ty * 4 + i) : (64 + ty * 4 + i - 4);
        int m = m_base + ml;
        if (m >= M) continue;
        size_t crow;
        if (cmode == 0) crow = (size_t)m;
        else { int bb = m / DEC_T, tt = m - bb * DEC_T; crow = (size_t)bb * SRC_T + tt + 1; }
        float* crp = C + crow * (size_t)N;
        float accf[8];
        unpack2(accf[0], accf[1], acc2[i][0]);
        unpack2(accf[2], accf[3], acc2[i][1]);
        unpack2(accf[4], accf[5], acc2[i][2]);
        unpack2(accf[6], accf[7], acc2[i][3]);
        #pragma unroll
        for (int jg = 0; jg < 2; jg++) {
            int n = n_base + jg * 64 + tx * 4;
            if (n < N) {
                float4 v;
                v.x = accf[jg * 4 + 0] + bias[n + 0];
                v.y = accf[jg * 4 + 1] + bias[n + 1];
                v.z = accf[jg * 4 + 2] + bias[n + 2];
                v.w = accf[jg * 4 + 3] + bias[n + 3];
                *(float4*)(crp + n) = v;
            }
        }
    }
}

// ---------------- persistent GRU layer recurrence ----------------
__global__ void __launch_bounds__(256) gru_layer_kernel(
    const float* __restrict__ gi, const float* __restrict__ WhhT,
    const float* __restrict__ bhh, const float* __restrict__ hinit,
    float* __restrict__ Y, float* __restrict__ hfinal, int T) {
    __shared__ float sh_hT[64][65];   // [k][m]  (65-stride: conflict-free stores; scalar reads)
    __shared__ float sh_w[64][96];    // [k][n]  loop-invariant weight tile
    int blk = blockIdx.x, tid = threadIdx.x;

    // this thread owns exactly one state element e (RBLK*256 == BATCH*HID)
    const int e = blk * 256 + tid;
    const int b = e >> 9, j = e & 511;
    float hreg = hinit ? hinit[e] : 0.0f;
    st_cg(&g_h[e], hreg);

    const float bh_r = bhh[j];
    const float bh_z = bhh[512 + j];
    const float bh_n = bhh[1024 + j];

    const int kc = blk >> 4, nt = blk & 15;
    const int k0 = kc * 64, n0 = nt * 96;
    const int tx = tid & 15, ty = tid >> 4;   // tx: 6-wide n, ty: 4-wide m

    // load weight tile once (invariant across all T steps)
    #pragma unroll
    for (int r = 0; r < 24; ++r) {
        int idx = r * 256 + tid;
        int k = idx / 96, n = idx - k * 96;
        sh_w[k][n] = WhhT[(size_t)(k0 + k) * G3 + n0 + n];
    }
    gbar();

    for (int t = 0; t < T; ++t) {
        const float* gir = gi + ((size_t)b * T + t) * G3;
        float gi_r = __ldg(gir + j);
        float gi_z = __ldg(gir + 512 + j);
        float gi_n = __ldg(gir + 1024 + j);

        // ---- phase A: partial gh = h[:, k0:k0+64] @ WhhT[k0:k0+64, n0:n0+96]
        #pragma unroll
        for (int r = 0; r < 16; ++r) {
            int idx = r * 256 + tid;
            int m = idx >> 6, k = idx & 63;
            sh_hT[k][m] = ld_cg(&g_h[m * HID + k0 + k]);
        }
        __syncthreads();
        u64 acc2[4][3] = {};              // packed pairs along n (6 -> 3)
        #pragma unroll
        for (int k = 0; k < 64; ++k) {
            float am[4];
            #pragma unroll
            for (int i = 0; i < 4; i++) am[i] = sh_hT[k][ty * 4 + i];
            float2 b01 = ld_shared_f2(&sh_w[k][tx * 6 + 0]);
            float2 b23 = ld_shared_f2(&sh_w[k][tx * 6 + 2]);
            float2 b45 = ld_shared_f2(&sh_w[k][tx * 6 + 4]);
            u64 bb2[3] = { pack2(b01.x, b01.y), pack2(b23.x, b23.y), pack2(b45.x, b45.y) };
            #pragma unroll
            for (int i = 0; i < 4; i++) {
                u64 a2 = pack2(am[i], am[i]);
                #pragma unroll
                for (int jn = 0; jn < 3; jn++)
                    acc2[i][jn] = ffma2(a2, bb2[jn], acc2[i][jn]);
            }
        }
        #pragma unroll
        for (int i = 0; i < 4; i++) {
            int m = ty * 4 + i;
            float* dst = &g_ghp[kc][m * G3 + n0 + tx * 6];
            float v0, v1;
            unpack2(v0, v1, acc2[i][0]); st_cg(dst + 0, v0); st_cg(dst + 1, v1);
            unpack2(v0, v1, acc2[i][1]); st_cg(dst + 2, v0); st_cg(dst + 3, v1);
            unpack2(v0, v1, acc2[i][2]); st_cg(dst + 4, v0); st_cg(dst + 5, v1);
        }
        gbar();
        // ---- phase B: gates + state update (one thread per (b, j))
        {
            float s0 = 0.f, s1 = 0.f, s2 = 0.f;
            #pragma unroll
            for (int c = 0; c < 8; c++) {
                const float* p = &g_ghp[c][b * G3];
                s0 += ld_cg(p + j);
                s1 += ld_cg(p + 512 + j);
                s2 += ld_cg(p + 1024 + j);
            }
            float r = 1.f / (1.f + __expf(-(gi_r + s0 + bh_r)));
            float z = 1.f / (1.f + __expf(-(gi_z + s1 + bh_z)));
            float nn = tanhf(gi_n + r * (s2 + bh_n));
            float hn = (1.f - z) * nn + z * hreg;
            Y[((size_t)b * T + t) * HID + j] = hn;
            st_cg(&g_h[e], hn);
            hreg = hn;
        }
        gbar();
    }
    hfinal[e] = hreg;
}

// ---------------- zero t=0 output plane ----------------
__global__ void zero_t0_kernel(float* __restrict__ out) {
    int idx = blockIdx.x * 256 + threadIdx.x;
    if (idx < BATCH * VOCAB) {
        int b = idx / VOCAB, v = idx - b * VOCAB;
        out[(size_t)b * SRC_T * VOCAB + v] = 0.0f;
    }
}

// ---------------- host driver ----------------
extern "C" void kernel_launch(void* const* d_in, const int* in_sizes, int n_in,
                              void* d_out, int out_size) {
    const int*   src     = (const int*)  d_in[0];
    const int*   trg     = (const int*)  d_in[1];
    const float* enc_emb = (const float*)d_in[2];
    const float* enc_Wih = (const float*)d_in[3];
    const float* enc_Whh = (const float*)d_in[4];
    const float* enc_bih = (const float*)d_in[5];
    const float* enc_bhh = (const float*)d_in[6];
    const float* dec_emb = (const float*)d_in[7];
    const float* dec_Wih = (const float*)d_in[8];
    const float* dec_Whh = (const float*)d_in[9];
    const float* dec_bih = (const float*)d_in[10];
    const float* dec_bhh = (const float*)d_in[11];
    const float* fc_W    = (const float*)d_in[12];
    const float* fc_b    = (const float*)d_in[13];
    float* out = (float*)d_out;

    float *pX, *pY, *pgi, *pWTih, *pWThh, *pfcT, *phenc, *phdec;
    cudaGetSymbolAddress((void**)&pX,    g_X);
    cudaGetSymbolAddress((void**)&pY,    g_Ybuf);
    cudaGetSymbolAddress((void**)&pgi,   g_gi);
    cudaGetSymbolAddress((void**)&pWTih, g_WTih);
    cudaGetSymbolAddress((void**)&pWThh, g_WThh);
    cudaGetSymbolAddress((void**)&pfcT,  g_fcT);
    cudaGetSymbolAddress((void**)&phenc, g_hid_enc);
    cudaGetSymbolAddress((void**)&phdec, g_hid_dec);

    dim3 tb(32, 8);
    dim3 tW(EMB / 32, G3 / 32);          // transpose grids for Wih/Whh (1536x512)

    // ----- encoder -----
    embed_kernel<<<BATCH * SRC_T, 128>>>(src, SRC_T, enc_emb, pX, SRC_T);
    for (int l = 0; l < NLAYERS; l++) {
        transpose_kernel<<<tW, tb>>>(enc_Wih + (size_t)l * G3 * EMB, pWTih, G3, EMB);
        transpose_kernel<<<tW, tb>>>(enc_Whh + (size_t)l * G3 * HID, pWThh, G3, HID);
        const float* Ain = (l == 0) ? pX : pY;
        float*       Yout = (l == 0) ? pY : pX;
        sgemm_bias<<<dim3(G3 / 128, (BATCH * SRC_T + 127) / 128), 256>>>(
            Ain, pWTih, pgi, enc_bih + l * G3, BATCH * SRC_T, G3, EMB, 0);
        gru_layer_kernel<<<RBLK, 256>>>(pgi, pWThh, enc_bhh + l * G3, nullptr,
                                        Yout, phenc + l * BATCH * HID, SRC_T);
    }

    // ----- decoder -----
    embed_kernel<<<BATCH * DEC_T, 128>>>(trg, SRC_T, dec_emb, pX, DEC_T);
    const int MD = BATCH * DEC_T;   // 8128
    for (int l = 0; l < NLAYERS; l++) {
        transpose_kernel<<<tW, tb>>>(dec_Wih + (size_t)l * G3 * EMB, pWTih, G3, EMB);
        transpose_kernel<<<tW, tb>>>(dec_Whh + (size_t)l * G3 * HID, pWThh, G3, HID);
        const float* Ain = (l == 0) ? pX : pY;
        float*       Yout = (l == 0) ? pY : pX;
        sgemm_bias<<<dim3(G3 / 128, (MD + 127) / 128), 256>>>(
            Ain, pWTih, pgi, dec_bih + l * G3, MD, G3, EMB, 0);
        gru_layer_kernel<<<RBLK, 256>>>(pgi, pWThh, dec_bhh + l * G3,
                                        phenc + l * BATCH * HID,
                                        Yout, phdec + l * BATCH * HID, DEC_T);
    }

    // ----- output head -----
    zero_t0_kernel<<<(BATCH * VOCAB + 255) / 256, 256>>>(out);
    transpose_kernel<<<dim3(HID / 32, (VOCAB + 31) / 32), tb>>>(fc_W, pfcT, VOCAB, HID);
    sgemm_bias<<<dim3((VOCAB + 127) / 128, (MD + 127) / 128), 256>>>(
        pX, pfcT, out, fc_b, MD, VOCAB, HID, 1);
}